// round 12
// baseline (speedup 1.0000x reference)
#include <cuda_runtime.h>
#include <cuda_bf16.h>
#include <math.h>
#include <stdint.h>

// Problem constants
#define T_TOK 49152          // B*S*N = 2*24*1024
#define HID   512
#define NEXP  8
#define MOEI  1024
#define SHI   2048
#define NSLOT (2 * T_TOK)    // top-2 -> exactly 2 slots per token

// ---------------------------------------------------------------------------
// Scratch (static __device__ arrays; no allocation anywhere)
// ---------------------------------------------------------------------------
__device__ float g_bufA[100663296];             // h for MoE (2T x MOEI)
__device__ float g_bufB[100663296];             // h for shared (T x SHI)
__device__ float g_y  [(size_t)NSLOT * HID];    // per-slot expert output
__device__ int   g_topk_idx[NSLOT];
__device__ float g_topk_w [NSLOT];
__device__ float g_sig    [T_TOK];
__device__ int   g_counts [NEXP];
__device__ int   g_offsets[NEXP];
__device__ int   g_cursor [NEXP];
__device__ int   g_slot_token[NSLOT];           // slot -> token
__device__ int   g_slot_of   [NSLOT];           // (token,k) -> slot

// ---------------------------------------------------------------------------
// helpers
// ---------------------------------------------------------------------------
__device__ __forceinline__ uint32_t f2tf32(float x) {
    uint32_t r;
    asm("cvt.rna.tf32.f32 %0, %1;" : "=r"(r) : "f"(x));
    return r;
}

__device__ __forceinline__ void mma_tf32(float* c, const uint32_t* a,
                                         uint32_t b0, uint32_t b1) {
    asm volatile(
        "mma.sync.aligned.m16n8k8.row.col.f32.tf32.tf32.f32 "
        "{%0,%1,%2,%3},{%4,%5,%6,%7},{%8,%9},{%0,%1,%2,%3};"
        : "+f"(c[0]), "+f"(c[1]), "+f"(c[2]), "+f"(c[3])
        : "r"(a[0]), "r"(a[1]), "r"(a[2]), "r"(a[3]), "r"(b0), "r"(b1));
}

__device__ __forceinline__ float silu(float x) {
    return x * (1.f / (1.f + __expf(-x)));
}

// tensor-path fraction: tensor tiles = (nt*4)/5
__device__ __forceinline__ int tsplit(int nt) { return (nt * 4) / 5; }

// ---------------------------------------------------------------------------
// 0) zero counters
// ---------------------------------------------------------------------------
__global__ void init_kernel() {
    int i = threadIdx.x;
    if (i < NEXP) { g_counts[i] = 0; g_cursor[i] = 0; }
}

// ---------------------------------------------------------------------------
// 1) router
// ---------------------------------------------------------------------------
__global__ void __launch_bounds__(256) router_kernel(
    const float* __restrict__ x, const float* __restrict__ gw,
    const float* __restrict__ sg, float* __restrict__ logits_out)
{
    __shared__ float s_gw[HID * NEXP];
    __shared__ float s_sg[HID];
    for (int i = threadIdx.x; i < HID * NEXP; i += 256) s_gw[i] = gw[i];
    for (int i = threadIdx.x; i < HID; i += 256) s_sg[i] = sg[i];
    __syncthreads();

    int warp = threadIdx.x >> 5, lane = threadIdx.x & 31;
    int t = blockIdx.x * 8 + warp;
    const float* xr = x + (size_t)t * HID;

    float acc[NEXP];
#pragma unroll
    for (int e = 0; e < NEXP; e++) acc[e] = 0.f;
    float accs = 0.f;

#pragma unroll 4
    for (int i = 0; i < 16; i++) {
        int h = i * 32 + lane;
        float xv = xr[h];
#pragma unroll
        for (int e = 0; e < NEXP; e++) acc[e] += xv * s_gw[h * NEXP + e];
        accs += xv * s_sg[h];
    }
#pragma unroll
    for (int off = 16; off; off >>= 1) {
#pragma unroll
        for (int e = 0; e < NEXP; e++)
            acc[e] += __shfl_xor_sync(0xffffffff, acc[e], off);
        accs += __shfl_xor_sync(0xffffffff, accs, off);
    }

    if (lane == 0) {
        if (logits_out) {
#pragma unroll
            for (int e = 0; e < NEXP; e++) logits_out[(size_t)t * NEXP + e] = acc[e];
        }
        float m = acc[0];
#pragma unroll
        for (int e = 1; e < NEXP; e++) m = fmaxf(m, acc[e]);
        float p[NEXP], sum = 0.f;
#pragma unroll
        for (int e = 0; e < NEXP; e++) { p[e] = expf(acc[e] - m); sum += p[e]; }
        float inv = 1.f / sum;
#pragma unroll
        for (int e = 0; e < NEXP; e++) p[e] *= inv;

        int i1 = 0;
#pragma unroll
        for (int e = 1; e < NEXP; e++) if (p[e] > p[i1]) i1 = e;
        int i2 = (i1 == 0) ? 1 : 0;
#pragma unroll
        for (int e = 0; e < NEXP; e++) if (e != i1 && e != i2 && p[e] > p[i2]) i2 = e;

        g_topk_idx[2 * t]     = i1; g_topk_w[2 * t]     = p[i1];
        g_topk_idx[2 * t + 1] = i2; g_topk_w[2 * t + 1] = p[i2];
        atomicAdd(&g_counts[i1], 1);
        atomicAdd(&g_counts[i2], 1);
        g_sig[t] = 1.f / (1.f + expf(-accs));
    }
}

// ---------------------------------------------------------------------------
// 2) prefix, 3) scatter
// ---------------------------------------------------------------------------
__global__ void prefix_kernel() {
    if (threadIdx.x == 0) {
        int s = 0;
        for (int e = 0; e < NEXP; e++) { g_offsets[e] = s; g_cursor[e] = s; s += g_counts[e]; }
    }
}

__global__ void scatter_kernel() {
    int t = blockIdx.x * 256 + threadIdx.x;
    if (t >= T_TOK) return;
#pragma unroll
    for (int k = 0; k < 2; k++) {
        int e = g_topk_idx[2 * t + k];
        int pos = atomicAdd(&g_cursor[e], 1);
        g_slot_token[pos] = t;
        g_slot_of[2 * t + k] = pos;
    }
}

// ---------------------------------------------------------------------------
// 4a) HYBRID dual GEMM + SwiGLU. Row-tiles split between tensor path (tf32
//     mma, first 4/5 of tiles) and fp32-FFMA path (last 1/5) so both pipes
//     run concurrently. Block tile 128x64, 256 threads.
//     z=0..7 MoE experts (gathered, bufA), z=8..9 shared halves (bufB).
//     (bufA and bufB are disjoint outputs -> merging is race-free.)
// ---------------------------------------------------------------------------
#define DUAL_BUF (128 * 36 + 2 * 32 * 72)       // floats per buffer: 9216
#define DUAL_SMEM (2 * DUAL_BUF * 4)            // 73728 bytes

__global__ void __launch_bounds__(256, 2) dual_hybrid_kernel(
    const float* __restrict__ A,
    const float* __restrict__ W1m, const float* __restrict__ W3m, float* __restrict__ Cm,
    const float* __restrict__ W1s, const float* __restrict__ W3s, float* __restrict__ Cs)
{
    extern __shared__ float sm[];

    const int K = HID;
    int z = blockIdx.z;
    int M, base, N, col0, useGather;
    const float *B1p, *B3p;
    float* C;
    if (z < NEXP) {
        M = g_counts[z]; base = g_offsets[z]; useGather = 1;
        N = MOEI; col0 = blockIdx.x * 64;
        B1p = W1m + (size_t)z * HID * MOEI;
        B3p = W3m + (size_t)z * HID * MOEI;
        C = Cm;
    } else {
        M = T_TOK; base = 0; useGather = 0;
        N = SHI; col0 = (blockIdx.x + (z - NEXP) * 16) * 64;
        B1p = W1s; B3p = W3s;
        C = Cs;
    }
    int nt = (M + 127) >> 7;
    int y = blockIdx.y;
    if (y >= nt) return;
    int row0 = y * 128;
    int tid  = threadIdx.x;

    if (y < tsplit(nt)) {
        // ================= TENSOR PATH (tf32 mma) =================
        int lane = tid & 31;
        int wid  = tid >> 5;
        int wm   = (wid >> 1) * 32;
        int wn   = (wid & 1) * 32;

        const float* aptr[4];
        int asto[4];
#pragma unroll
        for (int j = 0; j < 4; j++) {
            int v = tid + j * 256;
            int r = v >> 3;
            int gr = row0 + r; if (gr > M - 1) gr = M - 1;
            long arow = useGather ? (long)g_slot_token[base + gr] : (long)(base + gr);
            aptr[j] = A + (size_t)arow * K + (v & 7) * 4;
            asto[j] = r * 36 + (v & 7) * 4;
        }
        const float* b1ptr[2]; const float* b3ptr[2];
        int bsto[2];
#pragma unroll
        for (int j = 0; j < 2; j++) {
            int v = tid + j * 256;
            size_t off = (size_t)(v >> 4) * N + col0 + (v & 15) * 4;
            b1ptr[j] = B1p + off;
            b3ptr[j] = B3p + off;
            bsto[j] = (v >> 4) * 72 + (v & 15) * 4;
        }

        float accg[2][4][4], accu[2][4][4];
#pragma unroll
        for (int mi = 0; mi < 2; mi++)
#pragma unroll
            for (int ni = 0; ni < 4; ni++)
#pragma unroll
                for (int q = 0; q < 4; q++) { accg[mi][ni][q] = 0.f; accu[mi][ni][q] = 0.f; }

        int nk = K >> 5;

        float4 sa[4], s1[2], s3[2];
#pragma unroll
        for (int j = 0; j < 4; j++) { sa[j] = *(const float4*)aptr[j]; aptr[j] += 32; }
#pragma unroll
        for (int j = 0; j < 2; j++) {
            s1[j] = *(const float4*)b1ptr[j]; b1ptr[j] += (size_t)32 * N;
            s3[j] = *(const float4*)b3ptr[j]; b3ptr[j] += (size_t)32 * N;
        }
        {
            float* Ab = sm;
            float* B1b = sm + 128 * 36;
            float* B3b = B1b + 32 * 72;
#pragma unroll
            for (int j = 0; j < 4; j++) {
                float* d = Ab + asto[j];
                d[0] = __uint_as_float(f2tf32(sa[j].x));
                d[1] = __uint_as_float(f2tf32(sa[j].y));
                d[2] = __uint_as_float(f2tf32(sa[j].z));
                d[3] = __uint_as_float(f2tf32(sa[j].w));
            }
#pragma unroll
            for (int j = 0; j < 2; j++) {
                float* d1 = B1b + bsto[j];
                d1[0] = __uint_as_float(f2tf32(s1[j].x));
                d1[1] = __uint_as_float(f2tf32(s1[j].y));
                d1[2] = __uint_as_float(f2tf32(s1[j].z));
                d1[3] = __uint_as_float(f2tf32(s1[j].w));
                float* d3 = B3b + bsto[j];
                d3[0] = __uint_as_float(f2tf32(s3[j].x));
                d3[1] = __uint_as_float(f2tf32(s3[j].y));
                d3[2] = __uint_as_float(f2tf32(s3[j].z));
                d3[3] = __uint_as_float(f2tf32(s3[j].w));
            }
        }
        __syncthreads();

        for (int kt = 0; kt < nk; kt++) {
            int cur = kt & 1;
            float* Ab  = sm + cur * DUAL_BUF;
            float* B1b = Ab + 128 * 36;
            float* B3b = B1b + 32 * 72;

            if (kt + 1 < nk) {
#pragma unroll
                for (int j = 0; j < 4; j++) { sa[j] = *(const float4*)aptr[j]; aptr[j] += 32; }
#pragma unroll
                for (int j = 0; j < 2; j++) {
                    s1[j] = *(const float4*)b1ptr[j]; b1ptr[j] += (size_t)32 * N;
                    s3[j] = *(const float4*)b3ptr[j]; b3ptr[j] += (size_t)32 * N;
                }
            }

#pragma unroll
            for (int ks = 0; ks < 4; ks++) {
                int k0 = ks * 8;
                uint32_t af[2][4];
#pragma unroll
                for (int mi = 0; mi < 2; mi++) {
                    int r = wm + mi * 16 + (lane >> 2);
                    int kc = k0 + (lane & 3);
                    af[mi][0] = __float_as_uint(Ab[r * 36 + kc]);
                    af[mi][1] = __float_as_uint(Ab[(r + 8) * 36 + kc]);
                    af[mi][2] = __float_as_uint(Ab[r * 36 + kc + 4]);
                    af[mi][3] = __float_as_uint(Ab[(r + 8) * 36 + kc + 4]);
                }
#pragma unroll
                for (int ni = 0; ni < 4; ni++) {
                    int c = wn + ni * 8 + (lane >> 2);
                    int kr = k0 + (lane & 3);
                    uint32_t g0 = __float_as_uint(B1b[kr * 72 + c]);
                    uint32_t g1 = __float_as_uint(B1b[(kr + 4) * 72 + c]);
                    uint32_t u0 = __float_as_uint(B3b[kr * 72 + c]);
                    uint32_t u1 = __float_as_uint(B3b[(kr + 4) * 72 + c]);
#pragma unroll
                    for (int mi = 0; mi < 2; mi++) {
                        mma_tf32(accg[mi][ni], af[mi], g0, g1);
                        mma_tf32(accu[mi][ni], af[mi], u0, u1);
                    }
                }
            }

            if (kt + 1 < nk) {
                float* Ab2  = sm + (cur ^ 1) * DUAL_BUF;
                float* B1b2 = Ab2 + 128 * 36;
                float* B3b2 = B1b2 + 32 * 72;
#pragma unroll
                for (int j = 0; j < 4; j++) {
                    float* d = Ab2 + asto[j];
                    d[0] = __uint_as_float(f2tf32(sa[j].x));
                    d[1] = __uint_as_float(f2tf32(sa[j].y));
                    d[2] = __uint_as_float(f2tf32(sa[j].z));
                    d[3] = __uint_as_float(f2tf32(sa[j].w));
                }
#pragma unroll
                for (int j = 0; j < 2; j++) {
                    float* d1 = B1b2 + bsto[j];
                    d1[0] = __uint_as_float(f2tf32(s1[j].x));
                    d1[1] = __uint_as_float(f2tf32(s1[j].y));
                    d1[2] = __uint_as_float(f2tf32(s1[j].z));
                    d1[3] = __uint_as_float(f2tf32(s1[j].w));
                    float* d3 = B3b2 + bsto[j];
                    d3[0] = __uint_as_float(f2tf32(s3[j].x));
                    d3[1] = __uint_as_float(f2tf32(s3[j].y));
                    d3[2] = __uint_as_float(f2tf32(s3[j].z));
                    d3[3] = __uint_as_float(f2tf32(s3[j].w));
                }
            }
            __syncthreads();
        }

#pragma unroll
        for (int mi = 0; mi < 2; mi++) {
            int r0 = row0 + wm + mi * 16 + (lane >> 2);
            int r1 = r0 + 8;
#pragma unroll
            for (int ni = 0; ni < 4; ni++) {
                int c = col0 + wn + ni * 8 + (lane & 3) * 2;
                if (r0 < M) {
                    float* p = C + (size_t)(base + r0) * N + c;
                    p[0] = silu(accg[mi][ni][0]) * accu[mi][ni][0];
                    p[1] = silu(accg[mi][ni][1]) * accu[mi][ni][1];
                }
                if (r1 < M) {
                    float* p = C + (size_t)(base + r1) * N + c;
                    p[0] = silu(accg[mi][ni][2]) * accu[mi][ni][2];
                    p[1] = silu(accg[mi][ni][3]) * accu[mi][ni][3];
                }
            }
        }
    } else {
        // ================= FMA PATH (fp32 FFMA, dual, 8x4/thread) ============
        float* Asf = sm;                     // [16][132]
        float* B1f = sm + 16 * 132;          // [16][68]
        float* B3f = B1f + 16 * 68;          // [16][68]
        int ty8 = (tid >> 4) * 8;
        int tx4 = (tid & 15) * 4;

        const float* aq[2];
#pragma unroll
        for (int j = 0; j < 2; j++) {
            int v = tid + j * 256;
            int r = v >> 2;
            int gr = row0 + r; if (gr > M - 1) gr = M - 1;
            long arow = useGather ? (long)g_slot_token[base + gr] : (long)(base + gr);
            aq[j] = A + (size_t)arow * K + (v & 3) * 4;
        }
        const float* b1q = B1p + (size_t)(tid >> 4) * N + col0 + (tid & 15) * 4;
        const float* b3q = B3p + (size_t)(tid >> 4) * N + col0 + (tid & 15) * 4;

        float gA[8][4], uA[8][4];
#pragma unroll
        for (int i = 0; i < 8; i++)
#pragma unroll
            for (int j = 0; j < 4; j++) { gA[i][j] = 0.f; uA[i][j] = 0.f; }

        int nk2 = K >> 4;
        float4 ra[2], r1v, r3v;
#pragma unroll
        for (int j = 0; j < 2; j++) { ra[j] = *(const float4*)aq[j]; aq[j] += 16; }
        r1v = *(const float4*)b1q; b1q += (size_t)16 * N;
        r3v = *(const float4*)b3q; b3q += (size_t)16 * N;

        for (int kt = 0; kt < nk2; kt++) {
#pragma unroll
            for (int j = 0; j < 2; j++) {
                int v = tid + j * 256;
                int r = v >> 2, kq = (v & 3) * 4;
                Asf[(kq + 0) * 132 + r] = ra[j].x;
                Asf[(kq + 1) * 132 + r] = ra[j].y;
                Asf[(kq + 2) * 132 + r] = ra[j].z;
                Asf[(kq + 3) * 132 + r] = ra[j].w;
            }
            {
                int kr = tid >> 4, cq = (tid & 15) * 4;
                float* d1 = &B1f[kr * 68 + cq];
                d1[0] = r1v.x; d1[1] = r1v.y; d1[2] = r1v.z; d1[3] = r1v.w;
                float* d3 = &B3f[kr * 68 + cq];
                d3[0] = r3v.x; d3[1] = r3v.y; d3[2] = r3v.z; d3[3] = r3v.w;
            }
            __syncthreads();

            if (kt + 1 < nk2) {
#pragma unroll
                for (int j = 0; j < 2; j++) { ra[j] = *(const float4*)aq[j]; aq[j] += 16; }
                r1v = *(const float4*)b1q; b1q += (size_t)16 * N;
                r3v = *(const float4*)b3q; b3q += (size_t)16 * N;
            }

#pragma unroll
            for (int k = 0; k < 16; k++) {
                float4 a0 = *(const float4*)&Asf[k * 132 + ty8];
                float4 a1 = *(const float4*)&Asf[k * 132 + ty8 + 4];
                float4 bv1 = *(const float4*)&B1f[k * 68 + tx4];
                float4 bv3 = *(const float4*)&B3f[k * 68 + tx4];
                float a[8] = {a0.x, a0.y, a0.z, a0.w, a1.x, a1.y, a1.z, a1.w};
                float b1a[4] = {bv1.x, bv1.y, bv1.z, bv1.w};
                float b3a[4] = {bv3.x, bv3.y, bv3.z, bv3.w};
#pragma unroll
                for (int i = 0; i < 8; i++)
#pragma unroll
                    for (int j = 0; j < 4; j++) {
                        gA[i][j] += a[i] * b1a[j];
                        uA[i][j] += a[i] * b3a[j];
                    }
            }
            __syncthreads();
        }

#pragma unroll
        for (int i = 0; i < 8; i++) {
            int r = row0 + ty8 + i;
            if (r < M) {
                float* p = C + (size_t)(base + r) * N + col0 + tx4;
                p[0] = silu(gA[i][0]) * uA[i][0];
                p[1] = silu(gA[i][1]) * uA[i][1];
                p[2] = silu(gA[i][2]) * uA[i][2];
                p[3] = silu(gA[i][3]) * uA[i][3];
            }
        }
    }
}

// ---------------------------------------------------------------------------
// 4b) HYBRID down-projection GEMM with zbase (two launches: MoE z=0..7
//     producing g_y, THEN shared z=8 reading g_y in the fused combine —
//     the launch boundary is the producer->consumer sync).
// ---------------------------------------------------------------------------
#define SG_BUF (128 * 36 + 32 * 136)            // floats per buffer: 8960
#define SG_SMEM (2 * SG_BUF * 4)                // 71680 bytes

__global__ void __launch_bounds__(256, 2) sgemm_hybrid_kernel(
    const float* __restrict__ Am, const float* __restrict__ Bm, float* __restrict__ Cm,
    const float* __restrict__ Ash, const float* __restrict__ Bsh, float* __restrict__ Csh,
    int zbase)
{
    extern __shared__ float sm[];

    const int N = HID;
    int z = blockIdx.z + zbase;
    int M, base, K, fuse;
    const float *A, *Bp;
    float* C;
    if (z < NEXP) {
        M = g_counts[z]; base = g_offsets[z]; K = MOEI; fuse = 0;
        A = Am; Bp = Bm + (size_t)z * MOEI * HID; C = Cm;
    } else {
        M = T_TOK; base = 0; K = SHI; fuse = 1;
        A = Ash; Bp = Bsh; C = Csh;
    }
    int nt = (M + 127) >> 7;
    int y = blockIdx.y;
    if (y >= nt) return;
    int row0 = y * 128;
    int col0 = blockIdx.x * 128;
    int tid  = threadIdx.x;

    if (y < tsplit(nt)) {
        // ================= TENSOR PATH =================
        int lane = tid & 31;
        int wid  = tid >> 5;
        int wm   = (wid & 1) * 64;
        int wn   = (wid >> 1) * 32;

        const float* aptr[4];
        int asto[4];
#pragma unroll
        for (int j = 0; j < 4; j++) {
            int v = tid + j * 256;
            int r = v >> 3;
            int gr = row0 + r; if (gr > M - 1) gr = M - 1;
            aptr[j] = A + (size_t)(base + gr) * K + (v & 7) * 4;
            asto[j] = r * 36 + (v & 7) * 4;
        }
        const float* bptr[4];
        int bsto[4];
#pragma unroll
        for (int j = 0; j < 4; j++) {
            int v = tid + j * 256;
            bptr[j] = Bp + (size_t)(v >> 5) * N + col0 + (v & 31) * 4;
            bsto[j] = (v >> 5) * 136 + (v & 31) * 4;
        }

        float acc[4][4][4];
#pragma unroll
        for (int mi = 0; mi < 4; mi++)
#pragma unroll
            for (int ni = 0; ni < 4; ni++)
#pragma unroll
                for (int q = 0; q < 4; q++) acc[mi][ni][q] = 0.f;

        int nk = K >> 5;

        float4 sa[4], sb[4];
#pragma unroll
        for (int j = 0; j < 4; j++) { sa[j] = *(const float4*)aptr[j]; aptr[j] += 32; }
#pragma unroll
        for (int j = 0; j < 4; j++) { sb[j] = *(const float4*)bptr[j]; bptr[j] += (size_t)32 * N; }
        {
            float* Ab = sm;
            float* Bb = sm + 128 * 36;
#pragma unroll
            for (int j = 0; j < 4; j++) {
                float* d = Ab + asto[j];
                d[0] = __uint_as_float(f2tf32(sa[j].x));
                d[1] = __uint_as_float(f2tf32(sa[j].y));
                d[2] = __uint_as_float(f2tf32(sa[j].z));
                d[3] = __uint_as_float(f2tf32(sa[j].w));
            }
#pragma unroll
            for (int j = 0; j < 4; j++) {
                float* d = Bb + bsto[j];
                d[0] = __uint_as_float(f2tf32(sb[j].x));
                d[1] = __uint_as_float(f2tf32(sb[j].y));
                d[2] = __uint_as_float(f2tf32(sb[j].z));
                d[3] = __uint_as_float(f2tf32(sb[j].w));
            }
        }
        __syncthreads();

        for (int kt = 0; kt < nk; kt++) {
            int cur = kt & 1;
            float* Ab = sm + cur * SG_BUF;
            float* Bb = Ab + 128 * 36;

            if (kt + 1 < nk) {
#pragma unroll
                for (int j = 0; j < 4; j++) { sa[j] = *(const float4*)aptr[j]; aptr[j] += 32; }
#pragma unroll
                for (int j = 0; j < 4; j++) { sb[j] = *(const float4*)bptr[j]; bptr[j] += (size_t)32 * N; }
            }

#pragma unroll
            for (int ks = 0; ks < 4; ks++) {
                int k0 = ks * 8;
                uint32_t af[4][4];
#pragma unroll
                for (int mi = 0; mi < 4; mi++) {
                    int r = wm + mi * 16 + (lane >> 2);
                    int kc = k0 + (lane & 3);
                    af[mi][0] = __float_as_uint(Ab[r * 36 + kc]);
                    af[mi][1] = __float_as_uint(Ab[(r + 8) * 36 + kc]);
                    af[mi][2] = __float_as_uint(Ab[r * 36 + kc + 4]);
                    af[mi][3] = __float_as_uint(Ab[(r + 8) * 36 + kc + 4]);
                }
#pragma unroll
                for (int ni = 0; ni < 4; ni++) {
                    int c = wn + ni * 8 + (lane >> 2);
                    int kr = k0 + (lane & 3);
                    uint32_t b0 = __float_as_uint(Bb[kr * 136 + c]);
                    uint32_t b1 = __float_as_uint(Bb[(kr + 4) * 136 + c]);
#pragma unroll
                    for (int mi = 0; mi < 4; mi++)
                        mma_tf32(acc[mi][ni], af[mi], b0, b1);
                }
            }

            if (kt + 1 < nk) {
                float* Ab2 = sm + (cur ^ 1) * SG_BUF;
                float* Bb2 = Ab2 + 128 * 36;
#pragma unroll
                for (int j = 0; j < 4; j++) {
                    float* d = Ab2 + asto[j];
                    d[0] = __uint_as_float(f2tf32(sa[j].x));
                    d[1] = __uint_as_float(f2tf32(sa[j].y));
                    d[2] = __uint_as_float(f2tf32(sa[j].z));
                    d[3] = __uint_as_float(f2tf32(sa[j].w));
                }
#pragma unroll
                for (int j = 0; j < 4; j++) {
                    float* d = Bb2 + bsto[j];
                    d[0] = __uint_as_float(f2tf32(sb[j].x));
                    d[1] = __uint_as_float(f2tf32(sb[j].y));
                    d[2] = __uint_as_float(f2tf32(sb[j].z));
                    d[3] = __uint_as_float(f2tf32(sb[j].w));
                }
            }
            __syncthreads();
        }

#pragma unroll
        for (int mi = 0; mi < 4; mi++) {
            int r0 = row0 + wm + mi * 16 + (lane >> 2);
            int r1 = r0 + 8;
#pragma unroll
            for (int ni = 0; ni < 4; ni++) {
                int c = col0 + wn + ni * 8 + (lane & 3) * 2;
                if (!fuse) {
                    if (r0 < M) {
                        float* p = C + (size_t)(base + r0) * N + c;
                        p[0] = acc[mi][ni][0]; p[1] = acc[mi][ni][1];
                    }
                    if (r1 < M) {
                        float* p = C + (size_t)(base + r1) * N + c;
                        p[0] = acc[mi][ni][2]; p[1] = acc[mi][ni][3];
                    }
                } else {
                    if (r0 < M) {
                        int t = r0;
                        float w0 = g_topk_w[2 * t], w1 = g_topk_w[2 * t + 1];
                        int   s0 = g_slot_of[2 * t], s1 = g_slot_of[2 * t + 1];
                        float sg = g_sig[t];
                        float2 y0 = *(const float2*)&g_y[(size_t)s0 * HID + c];
                        float2 y1 = *(const float2*)&g_y[(size_t)s1 * HID + c];
                        float* p = C + (size_t)t * N + c;
                        p[0] = w0 * y0.x + w1 * y1.x + sg * acc[mi][ni][0];
                        p[1] = w0 * y0.y + w1 * y1.y + sg * acc[mi][ni][1];
                    }
                    if (r1 < M) {
                        int t = r1;
                        float w0 = g_topk_w[2 * t], w1 = g_topk_w[2 * t + 1];
                        int   s0 = g_slot_of[2 * t], s1 = g_slot_of[2 * t + 1];
                        float sg = g_sig[t];
                        float2 y0 = *(const float2*)&g_y[(size_t)s0 * HID + c];
                        float2 y1 = *(const float2*)&g_y[(size_t)s1 * HID + c];
                        float* p = C + (size_t)t * N + c;
                        p[0] = w0 * y0.x + w1 * y1.x + sg * acc[mi][ni][2];
                        p[1] = w0 * y0.y + w1 * y1.y + sg * acc[mi][ni][3];
                    }
                }
            }
        }
    } else {
        // ================= FMA PATH (fp32, 8x8/thread) =================
        float* Asf = sm;                 // [16][132]
        float* Bsf = sm + 16 * 132;      // [16][132]
        int ty8 = (tid >> 4) * 8;
        int tx8 = (tid & 15) * 8;

        const float* aq[2];
#pragma unroll
        for (int j = 0; j < 2; j++) {
            int v = tid + j * 256;
            int r = v >> 2;
            int gr = row0 + r; if (gr > M - 1) gr = M - 1;
            aq[j] = A + (size_t)(base + gr) * K + (v & 3) * 4;
        }
        const float* bq[2];
#pragma unroll
        for (int j = 0; j < 2; j++) {
            int v = tid + j * 256;
            bq[j] = Bp + (size_t)(v >> 5) * N + col0 + (v & 31) * 4;
        }

        float acc[8][8];
#pragma unroll
        for (int i = 0; i < 8; i++)
#pragma unroll
            for (int j = 0; j < 8; j++) acc[i][j] = 0.f;

        int nk2 = K >> 4;
        float4 ra[2], rb[2];
#pragma unroll
        for (int j = 0; j < 2; j++) { ra[j] = *(const float4*)aq[j]; aq[j] += 16; }
#pragma unroll
        for (int j = 0; j < 2; j++) { rb[j] = *(const float4*)bq[j]; bq[j] += (size_t)16 * N; }

        for (int kt = 0; kt < nk2; kt++) {
#pragma unroll
            for (int j = 0; j < 2; j++) {
                int v = tid + j * 256;
                int r = v >> 2, kq = (v & 3) * 4;
                Asf[(kq + 0) * 132 + r] = ra[j].x;
                Asf[(kq + 1) * 132 + r] = ra[j].y;
                Asf[(kq + 2) * 132 + r] = ra[j].z;
                Asf[(kq + 3) * 132 + r] = ra[j].w;
            }
#pragma unroll
            for (int j = 0; j < 2; j++) {
                int v = tid + j * 256;
                float* d = &Bsf[(v >> 5) * 132 + (v & 31) * 4];
                d[0] = rb[j].x; d[1] = rb[j].y; d[2] = rb[j].z; d[3] = rb[j].w;
            }
            __syncthreads();

            if (kt + 1 < nk2) {
#pragma unroll
                for (int j = 0; j < 2; j++) { ra[j] = *(const float4*)aq[j]; aq[j] += 16; }
#pragma unroll
                for (int j = 0; j < 2; j++) { rb[j] = *(const float4*)bq[j]; bq[j] += (size_t)16 * N; }
            }

#pragma unroll
            for (int k = 0; k < 16; k++) {
                float4 a0 = *(const float4*)&Asf[k * 132 + ty8];
                float4 a1 = *(const float4*)&Asf[k * 132 + ty8 + 4];
                float4 b0 = *(const float4*)&Bsf[k * 132 + tx8];
                float4 b1 = *(const float4*)&Bsf[k * 132 + tx8 + 4];
                float a[8] = {a0.x, a0.y, a0.z, a0.w, a1.x, a1.y, a1.z, a1.w};
                float b[8] = {b0.x, b0.y, b0.z, b0.w, b1.x, b1.y, b1.z, b1.w};
#pragma unroll
                for (int i = 0; i < 8; i++)
#pragma unroll
                    for (int j = 0; j < 8; j++) acc[i][j] += a[i] * b[j];
            }
            __syncthreads();
        }

#pragma unroll
        for (int i = 0; i < 8; i++) {
            int r = row0 + ty8 + i;
            if (r >= M) continue;
            int c = col0 + tx8;
            if (!fuse) {
                float* p = C + (size_t)(base + r) * N + c;
                p[0] = acc[i][0]; p[1] = acc[i][1]; p[2] = acc[i][2]; p[3] = acc[i][3];
                p[4] = acc[i][4]; p[5] = acc[i][5]; p[6] = acc[i][6]; p[7] = acc[i][7];
            } else {
                int t = r;
                float w0 = g_topk_w[2 * t], w1 = g_topk_w[2 * t + 1];
                int   s0 = g_slot_of[2 * t], s1 = g_slot_of[2 * t + 1];
                float sg = g_sig[t];
                const float* y0 = &g_y[(size_t)s0 * HID + c];
                const float* y1 = &g_y[(size_t)s1 * HID + c];
                float* p = C + (size_t)t * N + c;
#pragma unroll
                for (int j = 0; j < 8; j++)
                    p[j] = w0 * y0[j] + w1 * y1[j] + sg * acc[i][j];
            }
        }
    }
}

// ---------------------------------------------------------------------------
// launch
// ---------------------------------------------------------------------------
extern "C" void kernel_launch(void* const* d_in, const int* in_sizes, int n_in,
                              void* d_out, int out_size)
{
    const float* x     = (const float*)d_in[0];
    const float* gate  = (const float*)d_in[1];
    const float* w1    = (const float*)d_in[2];
    const float* w2    = (const float*)d_in[3];
    const float* w3    = (const float*)d_in[4];
    const float* sw1   = (const float*)d_in[5];
    const float* sw2   = (const float*)d_in[6];
    const float* sw3   = (const float*)d_in[7];
    const float* sgate = (const float*)d_in[8];
    float* out = (float*)d_out;

    float* logits = nullptr;
    if ((size_t)out_size >= (size_t)T_TOK * HID + (size_t)T_TOK * NEXP)
        logits = out + (size_t)T_TOK * HID;

    float *bufA, *bufB, *ybuf;
    cudaGetSymbolAddress((void**)&bufA, g_bufA);
    cudaGetSymbolAddress((void**)&bufB, g_bufB);
    cudaGetSymbolAddress((void**)&ybuf, g_y);

    static int smem_set = 0;
    if (!smem_set) {
        cudaFuncSetAttribute(dual_hybrid_kernel,
                             cudaFuncAttributeMaxDynamicSharedMemorySize, DUAL_SMEM);
        cudaFuncSetAttribute(sgemm_hybrid_kernel,
                             cudaFuncAttributeMaxDynamicSharedMemorySize, SG_SMEM);
        smem_set = 1;
    }

    init_kernel<<<1, 32>>>();
    router_kernel<<<T_TOK / 8, 256>>>(x, gate, sgate, logits);
    prefix_kernel<<<1, 32>>>();
    scatter_kernel<<<T_TOK / 256, 256>>>();

    // Stage A: hybrid tensor+fma SwiGLU. z=0..7 MoE -> bufA, z=8..9 shared -> bufB
    // (outputs disjoint -> safe to merge)
    dual_hybrid_kernel<<<dim3(16, T_TOK / 128, NEXP + 2), 256, DUAL_SMEM>>>(
        x, w1, w3, bufA, sw1, sw3, bufB);

    // Stage B launch 1: MoE down-proj -> g_y (must fully complete before combine)
    sgemm_hybrid_kernel<<<dim3(HID / 128, T_TOK / 128, NEXP), 256, SG_SMEM>>>(
        bufA, w2, ybuf, bufB, sw2, out, 0);

    // Stage B launch 2: shared down-proj + fused combine (reads g_y) -> out
    sgemm_hybrid_kernel<<<dim3(HID / 128, T_TOK / 128, 1), 256, SG_SMEM>>>(
        bufA, w2, ybuf, bufB, sw2, out, NEXP);

    (void)sgate;
}

// round 13
// speedup vs baseline: 1.3824x; 1.3824x over previous
#include <cuda_runtime.h>
#include <cuda_bf16.h>
#include <math.h>
#include <stdint.h>

// Problem constants
#define T_TOK 49152          // B*S*N = 2*24*1024
#define HID   512
#define NEXP  8
#define MOEI  1024
#define SHI   2048
#define NSLOT (2 * T_TOK)    // top-2 -> exactly 2 slots per token

// ---------------------------------------------------------------------------
// Scratch (static __device__ arrays; no allocation anywhere)
// ---------------------------------------------------------------------------
__device__ float g_bufA[100663296];             // h for MoE (2T x MOEI)
__device__ float g_bufB[100663296];             // h for shared (T x SHI)
__device__ float g_y  [(size_t)NSLOT * HID];    // per-slot expert output
__device__ int   g_topk_idx[NSLOT];
__device__ float g_topk_w [NSLOT];
__device__ float g_sig    [T_TOK];
__device__ int   g_counts [NEXP];
__device__ int   g_offsets[NEXP];
__device__ int   g_cursor [NEXP];
__device__ int   g_slot_token[NSLOT];           // slot -> token
__device__ int   g_slot_of   [NSLOT];           // (token,k) -> slot

// ---------------------------------------------------------------------------
// helpers
// ---------------------------------------------------------------------------
__device__ __forceinline__ uint32_t f2tf32(float x) {
    uint32_t r;
    asm("cvt.rna.tf32.f32 %0, %1;" : "=r"(r) : "f"(x));
    return r;
}

__device__ __forceinline__ void mma_tf32(float* c, const uint32_t* a,
                                         uint32_t b0, uint32_t b1) {
    asm volatile(
        "mma.sync.aligned.m16n8k8.row.col.f32.tf32.tf32.f32 "
        "{%0,%1,%2,%3},{%4,%5,%6,%7},{%8,%9},{%0,%1,%2,%3};"
        : "+f"(c[0]), "+f"(c[1]), "+f"(c[2]), "+f"(c[3])
        : "r"(a[0]), "r"(a[1]), "r"(a[2]), "r"(a[3]), "r"(b0), "r"(b1));
}

__device__ __forceinline__ float silu(float x) {
    return x * (1.f / (1.f + __expf(-x)));
}

// ---------------------------------------------------------------------------
// 0) zero counters
// ---------------------------------------------------------------------------
__global__ void init_kernel() {
    int i = threadIdx.x;
    if (i < NEXP) { g_counts[i] = 0; g_cursor[i] = 0; }
}

// ---------------------------------------------------------------------------
// 1) router
// ---------------------------------------------------------------------------
__global__ void __launch_bounds__(256) router_kernel(
    const float* __restrict__ x, const float* __restrict__ gw,
    const float* __restrict__ sg, float* __restrict__ logits_out)
{
    __shared__ float s_gw[HID * NEXP];
    __shared__ float s_sg[HID];
    for (int i = threadIdx.x; i < HID * NEXP; i += 256) s_gw[i] = gw[i];
    for (int i = threadIdx.x; i < HID; i += 256) s_sg[i] = sg[i];
    __syncthreads();

    int warp = threadIdx.x >> 5, lane = threadIdx.x & 31;
    int t = blockIdx.x * 8 + warp;
    const float* xr = x + (size_t)t * HID;

    float acc[NEXP];
#pragma unroll
    for (int e = 0; e < NEXP; e++) acc[e] = 0.f;
    float accs = 0.f;

#pragma unroll 4
    for (int i = 0; i < 16; i++) {
        int h = i * 32 + lane;
        float xv = xr[h];
#pragma unroll
        for (int e = 0; e < NEXP; e++) acc[e] += xv * s_gw[h * NEXP + e];
        accs += xv * s_sg[h];
    }
#pragma unroll
    for (int off = 16; off; off >>= 1) {
#pragma unroll
        for (int e = 0; e < NEXP; e++)
            acc[e] += __shfl_xor_sync(0xffffffff, acc[e], off);
        accs += __shfl_xor_sync(0xffffffff, accs, off);
    }

    if (lane == 0) {
        if (logits_out) {
#pragma unroll
            for (int e = 0; e < NEXP; e++) logits_out[(size_t)t * NEXP + e] = acc[e];
        }
        float m = acc[0];
#pragma unroll
        for (int e = 1; e < NEXP; e++) m = fmaxf(m, acc[e]);
        float p[NEXP], sum = 0.f;
#pragma unroll
        for (int e = 0; e < NEXP; e++) { p[e] = expf(acc[e] - m); sum += p[e]; }
        float inv = 1.f / sum;
#pragma unroll
        for (int e = 0; e < NEXP; e++) p[e] *= inv;

        int i1 = 0;
#pragma unroll
        for (int e = 1; e < NEXP; e++) if (p[e] > p[i1]) i1 = e;
        int i2 = (i1 == 0) ? 1 : 0;
#pragma unroll
        for (int e = 0; e < NEXP; e++) if (e != i1 && e != i2 && p[e] > p[i2]) i2 = e;

        g_topk_idx[2 * t]     = i1; g_topk_w[2 * t]     = p[i1];
        g_topk_idx[2 * t + 1] = i2; g_topk_w[2 * t + 1] = p[i2];
        atomicAdd(&g_counts[i1], 1);
        atomicAdd(&g_counts[i2], 1);
        g_sig[t] = 1.f / (1.f + expf(-accs));
    }
}

// ---------------------------------------------------------------------------
// 2) prefix, 3) scatter
// ---------------------------------------------------------------------------
__global__ void prefix_kernel() {
    if (threadIdx.x == 0) {
        int s = 0;
        for (int e = 0; e < NEXP; e++) { g_offsets[e] = s; g_cursor[e] = s; s += g_counts[e]; }
    }
}

__global__ void scatter_kernel() {
    int t = blockIdx.x * 256 + threadIdx.x;
    if (t >= T_TOK) return;
#pragma unroll
    for (int k = 0; k < 2; k++) {
        int e = g_topk_idx[2 * t + k];
        int pos = atomicAdd(&g_cursor[e], 1);
        g_slot_token[pos] = t;
        g_slot_of[2 * t + k] = pos;
    }
}

// ---------------------------------------------------------------------------
// 4a) dual tf32 GEMM + in-register SwiGLU, ping-pong smem (pure tensor).
//     MERGED launch: z=0..7 MoE experts (gathered, bufA), z=8..9 the two
//     column-halves of the shared expert (dense, bufB). K=HID compile-time.
// ---------------------------------------------------------------------------
#define DUAL_BUF (128 * 36 + 2 * 32 * 72)       // floats per buffer: 9216
#define DUAL_SMEM (2 * DUAL_BUF * 4)            // 73728 bytes

__global__ void __launch_bounds__(256, 2) dual_swiglu_kernel(
    const float* __restrict__ A,
    const float* __restrict__ W1m, const float* __restrict__ W3m, float* __restrict__ Cm,
    const float* __restrict__ W1s, const float* __restrict__ W3s, float* __restrict__ Cs)
{
    extern __shared__ float sm[];

    const int K = HID;
    int z = blockIdx.z;
    int M, base, N, col0, useGather;
    const float *B1p, *B3p;
    float* C;
    if (z < NEXP) {
        M = g_counts[z]; base = g_offsets[z]; useGather = 1;
        N = MOEI; col0 = blockIdx.x * 64;
        B1p = W1m + (size_t)z * HID * MOEI;
        B3p = W3m + (size_t)z * HID * MOEI;
        C = Cm;
    } else {
        M = T_TOK; base = 0; useGather = 0;
        N = SHI; col0 = (blockIdx.x + (z - NEXP) * 16) * 64;
        B1p = W1s; B3p = W3s;
        C = Cs;
    }
    int y = blockIdx.y;
    int row0 = y * 128;
    if (row0 >= M) return;

    int tid  = threadIdx.x;
    int lane = tid & 31;
    int wid  = tid >> 5;
    int wm   = (wid >> 1) * 32;
    int wn   = (wid & 1) * 32;

    const float* aptr[4];
    int asto[4];
#pragma unroll
    for (int j = 0; j < 4; j++) {
        int v = tid + j * 256;
        int r = v >> 3;
        int gr = row0 + r; if (gr > M - 1) gr = M - 1;
        long arow = useGather ? (long)g_slot_token[base + gr] : (long)(base + gr);
        aptr[j] = A + (size_t)arow * K + (v & 7) * 4;
        asto[j] = r * 36 + (v & 7) * 4;
    }
    const float* b1ptr[2]; const float* b3ptr[2];
    int bsto[2];
#pragma unroll
    for (int j = 0; j < 2; j++) {
        int v = tid + j * 256;
        size_t off = (size_t)(v >> 4) * N + col0 + (v & 15) * 4;
        b1ptr[j] = B1p + off;
        b3ptr[j] = B3p + off;
        bsto[j] = (v >> 4) * 72 + (v & 15) * 4;
    }

    float accg[2][4][4], accu[2][4][4];
#pragma unroll
    for (int mi = 0; mi < 2; mi++)
#pragma unroll
        for (int ni = 0; ni < 4; ni++)
#pragma unroll
            for (int q = 0; q < 4; q++) { accg[mi][ni][q] = 0.f; accu[mi][ni][q] = 0.f; }

    const int nk = K >> 5;          // 16, compile-time

    float4 sa[4], s1[2], s3[2];
#pragma unroll
    for (int j = 0; j < 4; j++) { sa[j] = *(const float4*)aptr[j]; aptr[j] += 32; }
#pragma unroll
    for (int j = 0; j < 2; j++) {
        s1[j] = *(const float4*)b1ptr[j]; b1ptr[j] += (size_t)32 * N;
        s3[j] = *(const float4*)b3ptr[j]; b3ptr[j] += (size_t)32 * N;
    }
    {
        float* Ab = sm;
        float* B1b = sm + 128 * 36;
        float* B3b = B1b + 32 * 72;
#pragma unroll
        for (int j = 0; j < 4; j++) {
            float* d = Ab + asto[j];
            d[0] = __uint_as_float(f2tf32(sa[j].x));
            d[1] = __uint_as_float(f2tf32(sa[j].y));
            d[2] = __uint_as_float(f2tf32(sa[j].z));
            d[3] = __uint_as_float(f2tf32(sa[j].w));
        }
#pragma unroll
        for (int j = 0; j < 2; j++) {
            float* d1 = B1b + bsto[j];
            d1[0] = __uint_as_float(f2tf32(s1[j].x));
            d1[1] = __uint_as_float(f2tf32(s1[j].y));
            d1[2] = __uint_as_float(f2tf32(s1[j].z));
            d1[3] = __uint_as_float(f2tf32(s1[j].w));
            float* d3 = B3b + bsto[j];
            d3[0] = __uint_as_float(f2tf32(s3[j].x));
            d3[1] = __uint_as_float(f2tf32(s3[j].y));
            d3[2] = __uint_as_float(f2tf32(s3[j].z));
            d3[3] = __uint_as_float(f2tf32(s3[j].w));
        }
    }
    __syncthreads();

    for (int kt = 0; kt < nk; kt++) {
        int cur = kt & 1;
        float* Ab  = sm + cur * DUAL_BUF;
        float* B1b = Ab + 128 * 36;
        float* B3b = B1b + 32 * 72;

        if (kt + 1 < nk) {
#pragma unroll
            for (int j = 0; j < 4; j++) { sa[j] = *(const float4*)aptr[j]; aptr[j] += 32; }
#pragma unroll
            for (int j = 0; j < 2; j++) {
                s1[j] = *(const float4*)b1ptr[j]; b1ptr[j] += (size_t)32 * N;
                s3[j] = *(const float4*)b3ptr[j]; b3ptr[j] += (size_t)32 * N;
            }
        }

#pragma unroll
        for (int ks = 0; ks < 4; ks++) {
            int k0 = ks * 8;
            uint32_t af[2][4];
#pragma unroll
            for (int mi = 0; mi < 2; mi++) {
                int r = wm + mi * 16 + (lane >> 2);
                int kc = k0 + (lane & 3);
                af[mi][0] = __float_as_uint(Ab[r * 36 + kc]);
                af[mi][1] = __float_as_uint(Ab[(r + 8) * 36 + kc]);
                af[mi][2] = __float_as_uint(Ab[r * 36 + kc + 4]);
                af[mi][3] = __float_as_uint(Ab[(r + 8) * 36 + kc + 4]);
            }
#pragma unroll
            for (int ni = 0; ni < 4; ni++) {
                int c = wn + ni * 8 + (lane >> 2);
                int kr = k0 + (lane & 3);
                uint32_t g0 = __float_as_uint(B1b[kr * 72 + c]);
                uint32_t g1 = __float_as_uint(B1b[(kr + 4) * 72 + c]);
                uint32_t u0 = __float_as_uint(B3b[kr * 72 + c]);
                uint32_t u1 = __float_as_uint(B3b[(kr + 4) * 72 + c]);
#pragma unroll
                for (int mi = 0; mi < 2; mi++) {
                    mma_tf32(accg[mi][ni], af[mi], g0, g1);
                    mma_tf32(accu[mi][ni], af[mi], u0, u1);
                }
            }
        }

        if (kt + 1 < nk) {
            float* Ab2  = sm + (cur ^ 1) * DUAL_BUF;
            float* B1b2 = Ab2 + 128 * 36;
            float* B3b2 = B1b2 + 32 * 72;
#pragma unroll
            for (int j = 0; j < 4; j++) {
                float* d = Ab2 + asto[j];
                d[0] = __uint_as_float(f2tf32(sa[j].x));
                d[1] = __uint_as_float(f2tf32(sa[j].y));
                d[2] = __uint_as_float(f2tf32(sa[j].z));
                d[3] = __uint_as_float(f2tf32(sa[j].w));
            }
#pragma unroll
            for (int j = 0; j < 2; j++) {
                float* d1 = B1b2 + bsto[j];
                d1[0] = __uint_as_float(f2tf32(s1[j].x));
                d1[1] = __uint_as_float(f2tf32(s1[j].y));
                d1[2] = __uint_as_float(f2tf32(s1[j].z));
                d1[3] = __uint_as_float(f2tf32(s1[j].w));
                float* d3 = B3b2 + bsto[j];
                d3[0] = __uint_as_float(f2tf32(s3[j].x));
                d3[1] = __uint_as_float(f2tf32(s3[j].y));
                d3[2] = __uint_as_float(f2tf32(s3[j].z));
                d3[3] = __uint_as_float(f2tf32(s3[j].w));
            }
        }
        __syncthreads();
    }

    // epilogue: h = silu(g) * u
#pragma unroll
    for (int mi = 0; mi < 2; mi++) {
        int r0 = row0 + wm + mi * 16 + (lane >> 2);
        int r1 = r0 + 8;
#pragma unroll
        for (int ni = 0; ni < 4; ni++) {
            int c = col0 + wn + ni * 8 + (lane & 3) * 2;
            if (r0 < M) {
                float* p = C + (size_t)(base + r0) * N + c;
                p[0] = silu(accg[mi][ni][0]) * accu[mi][ni][0];
                p[1] = silu(accg[mi][ni][1]) * accu[mi][ni][1];
            }
            if (r1 < M) {
                float* p = C + (size_t)(base + r1) * N + c;
                p[0] = silu(accg[mi][ni][2]) * accu[mi][ni][2];
                p[1] = silu(accg[mi][ni][3]) * accu[mi][ni][3];
            }
        }
    }
}

// ---------------------------------------------------------------------------
// 4b) plain tf32 GEMM, 128x128 tile, ping-pong smem, pure tensor.
//     Templated on K and FUSE so N/K/strides are compile-time.
//     FUSE=false: MoE down-proj over slot rows (M=g_counts[z], base=offsets).
//     FUSE=true : shared down-proj + fused final combine (M=T_TOK).
// ---------------------------------------------------------------------------
#define SG_BUF (128 * 36 + 32 * 136)            // floats per buffer: 8960
#define SG_SMEM (2 * SG_BUF * 4)                // 71680 bytes
#define SG_N HID

template<int KK, bool FUSE>
__global__ void __launch_bounds__(256, 2) sgemm_tc_kernel(
    const float* __restrict__ A, const float* __restrict__ B, float* __restrict__ C)
{
    extern __shared__ float sm[];

    const int N = SG_N;
    int z = blockIdx.z;
    int M, base;
    const float* Bp;
    if (!FUSE) { M = g_counts[z]; base = g_offsets[z]; Bp = B + (size_t)z * KK * SG_N; }
    else       { M = T_TOK;       base = 0;            Bp = B; }
    int row0 = blockIdx.y * 128;
    if (row0 >= M) return;
    int col0 = blockIdx.x * 128;

    int tid  = threadIdx.x;
    int lane = tid & 31;
    int wid  = tid >> 5;
    int wm   = (wid & 1) * 64;
    int wn   = (wid >> 1) * 32;

    const float* aptr[4];
    int asto[4];
#pragma unroll
    for (int j = 0; j < 4; j++) {
        int v = tid + j * 256;
        int r = v >> 3;
        int gr = row0 + r; if (gr > M - 1) gr = M - 1;
        aptr[j] = A + (size_t)(base + gr) * KK + (v & 7) * 4;
        asto[j] = r * 36 + (v & 7) * 4;
    }
    const float* bptr[4];
    int bsto[4];
#pragma unroll
    for (int j = 0; j < 4; j++) {
        int v = tid + j * 256;
        bptr[j] = Bp + (size_t)(v >> 5) * N + col0 + (v & 31) * 4;
        bsto[j] = (v >> 5) * 136 + (v & 31) * 4;
    }

    float acc[4][4][4];
#pragma unroll
    for (int mi = 0; mi < 4; mi++)
#pragma unroll
        for (int ni = 0; ni < 4; ni++)
#pragma unroll
            for (int q = 0; q < 4; q++) acc[mi][ni][q] = 0.f;

    const int nk = KK >> 5;         // compile-time

    float4 sa[4], sb[4];
#pragma unroll
    for (int j = 0; j < 4; j++) { sa[j] = *(const float4*)aptr[j]; aptr[j] += 32; }
#pragma unroll
    for (int j = 0; j < 4; j++) { sb[j] = *(const float4*)bptr[j]; bptr[j] += (size_t)32 * N; }
    {
        float* Ab = sm;
        float* Bb = sm + 128 * 36;
#pragma unroll
        for (int j = 0; j < 4; j++) {
            float* d = Ab + asto[j];
            d[0] = __uint_as_float(f2tf32(sa[j].x));
            d[1] = __uint_as_float(f2tf32(sa[j].y));
            d[2] = __uint_as_float(f2tf32(sa[j].z));
            d[3] = __uint_as_float(f2tf32(sa[j].w));
        }
#pragma unroll
        for (int j = 0; j < 4; j++) {
            float* d = Bb + bsto[j];
            d[0] = __uint_as_float(f2tf32(sb[j].x));
            d[1] = __uint_as_float(f2tf32(sb[j].y));
            d[2] = __uint_as_float(f2tf32(sb[j].z));
            d[3] = __uint_as_float(f2tf32(sb[j].w));
        }
    }
    __syncthreads();

    for (int kt = 0; kt < nk; kt++) {
        int cur = kt & 1;
        float* Ab = sm + cur * SG_BUF;
        float* Bb = Ab + 128 * 36;

        if (kt + 1 < nk) {
#pragma unroll
            for (int j = 0; j < 4; j++) { sa[j] = *(const float4*)aptr[j]; aptr[j] += 32; }
#pragma unroll
            for (int j = 0; j < 4; j++) { sb[j] = *(const float4*)bptr[j]; bptr[j] += (size_t)32 * N; }
        }

#pragma unroll
        for (int ks = 0; ks < 4; ks++) {
            int k0 = ks * 8;
            uint32_t af[4][4];
#pragma unroll
            for (int mi = 0; mi < 4; mi++) {
                int r = wm + mi * 16 + (lane >> 2);
                int kc = k0 + (lane & 3);
                af[mi][0] = __float_as_uint(Ab[r * 36 + kc]);
                af[mi][1] = __float_as_uint(Ab[(r + 8) * 36 + kc]);
                af[mi][2] = __float_as_uint(Ab[r * 36 + kc + 4]);
                af[mi][3] = __float_as_uint(Ab[(r + 8) * 36 + kc + 4]);
            }
#pragma unroll
            for (int ni = 0; ni < 4; ni++) {
                int c = wn + ni * 8 + (lane >> 2);
                int kr = k0 + (lane & 3);
                uint32_t b0 = __float_as_uint(Bb[kr * 136 + c]);
                uint32_t b1 = __float_as_uint(Bb[(kr + 4) * 136 + c]);
#pragma unroll
                for (int mi = 0; mi < 4; mi++)
                    mma_tf32(acc[mi][ni], af[mi], b0, b1);
            }
        }

        if (kt + 1 < nk) {
            float* Ab2 = sm + (cur ^ 1) * SG_BUF;
            float* Bb2 = Ab2 + 128 * 36;
#pragma unroll
            for (int j = 0; j < 4; j++) {
                float* d = Ab2 + asto[j];
                d[0] = __uint_as_float(f2tf32(sa[j].x));
                d[1] = __uint_as_float(f2tf32(sa[j].y));
                d[2] = __uint_as_float(f2tf32(sa[j].z));
                d[3] = __uint_as_float(f2tf32(sa[j].w));
            }
#pragma unroll
            for (int j = 0; j < 4; j++) {
                float* d = Bb2 + bsto[j];
                d[0] = __uint_as_float(f2tf32(sb[j].x));
                d[1] = __uint_as_float(f2tf32(sb[j].y));
                d[2] = __uint_as_float(f2tf32(sb[j].z));
                d[3] = __uint_as_float(f2tf32(sb[j].w));
            }
        }
        __syncthreads();
    }

    // epilogue
#pragma unroll
    for (int mi = 0; mi < 4; mi++) {
        int r0 = row0 + wm + mi * 16 + (lane >> 2);
        int r1 = r0 + 8;
#pragma unroll
        for (int ni = 0; ni < 4; ni++) {
            int c = col0 + wn + ni * 8 + (lane & 3) * 2;
            if (!FUSE) {
                if (r0 < M) {
                    float* p = C + (size_t)(base + r0) * N + c;
                    p[0] = acc[mi][ni][0]; p[1] = acc[mi][ni][1];
                }
                if (r1 < M) {
                    float* p = C + (size_t)(base + r1) * N + c;
                    p[0] = acc[mi][ni][2]; p[1] = acc[mi][ni][3];
                }
            } else {
                if (r0 < M) {
                    int t = r0;
                    float w0 = g_topk_w[2 * t], w1 = g_topk_w[2 * t + 1];
                    int   s0 = g_slot_of[2 * t], s1 = g_slot_of[2 * t + 1];
                    float sg = g_sig[t];
                    float2 y0 = *(const float2*)&g_y[(size_t)s0 * HID + c];
                    float2 y1 = *(const float2*)&g_y[(size_t)s1 * HID + c];
                    float* p = C + (size_t)t * N + c;
                    p[0] = w0 * y0.x + w1 * y1.x + sg * acc[mi][ni][0];
                    p[1] = w0 * y0.y + w1 * y1.y + sg * acc[mi][ni][1];
                }
                if (r1 < M) {
                    int t = r1;
                    float w0 = g_topk_w[2 * t], w1 = g_topk_w[2 * t + 1];
                    int   s0 = g_slot_of[2 * t], s1 = g_slot_of[2 * t + 1];
                    float sg = g_sig[t];
                    float2 y0 = *(const float2*)&g_y[(size_t)s0 * HID + c];
                    float2 y1 = *(const float2*)&g_y[(size_t)s1 * HID + c];
                    float* p = C + (size_t)t * N + c;
                    p[0] = w0 * y0.x + w1 * y1.x + sg * acc[mi][ni][2];
                    p[1] = w0 * y0.y + w1 * y1.y + sg * acc[mi][ni][3];
                }
            }
        }
    }
}

// ---------------------------------------------------------------------------
// launch
// ---------------------------------------------------------------------------
extern "C" void kernel_launch(void* const* d_in, const int* in_sizes, int n_in,
                              void* d_out, int out_size)
{
    const float* x     = (const float*)d_in[0];
    const float* gate  = (const float*)d_in[1];
    const float* w1    = (const float*)d_in[2];
    const float* w2    = (const float*)d_in[3];
    const float* w3    = (const float*)d_in[4];
    const float* sw1   = (const float*)d_in[5];
    const float* sw2   = (const float*)d_in[6];
    const float* sw3   = (const float*)d_in[7];
    const float* sgate = (const float*)d_in[8];
    float* out = (float*)d_out;

    float* logits = nullptr;
    if ((size_t)out_size >= (size_t)T_TOK * HID + (size_t)T_TOK * NEXP)
        logits = out + (size_t)T_TOK * HID;

    float *bufA, *bufB, *ybuf;
    cudaGetSymbolAddress((void**)&bufA, g_bufA);
    cudaGetSymbolAddress((void**)&bufB, g_bufB);
    cudaGetSymbolAddress((void**)&ybuf, g_y);

    static int smem_set = 0;
    if (!smem_set) {
        cudaFuncSetAttribute(dual_swiglu_kernel,
                             cudaFuncAttributeMaxDynamicSharedMemorySize, DUAL_SMEM);
        cudaFuncSetAttribute(sgemm_tc_kernel<MOEI, false>,
                             cudaFuncAttributeMaxDynamicSharedMemorySize, SG_SMEM);
        cudaFuncSetAttribute(sgemm_tc_kernel<SHI, true>,
                             cudaFuncAttributeMaxDynamicSharedMemorySize, SG_SMEM);
        smem_set = 1;
    }

    init_kernel<<<1, 32>>>();
    router_kernel<<<T_TOK / 8, 256>>>(x, gate, sgate, logits);
    prefix_kernel<<<1, 32>>>();
    scatter_kernel<<<T_TOK / 256, 256>>>();

    // Stage A merged: z=0..7 MoE experts -> bufA, z=8..9 shared halves -> bufB
    dual_swiglu_kernel<<<dim3(16, T_TOK / 128, NEXP + 2), 256, DUAL_SMEM>>>(
        x, w1, w3, bufA, sw1, sw3, bufB);

    // Stage B launch 1: MoE down-proj -> g_y
    sgemm_tc_kernel<MOEI, false><<<dim3(HID / 128, T_TOK / 128, NEXP), 256, SG_SMEM>>>(
        bufA, w2, ybuf);

    // Stage B launch 2: shared down-proj + fused final combine -> out
    sgemm_tc_kernel<SHI, true><<<dim3(HID / 128, T_TOK / 128, 1), 256, SG_SMEM>>>(
        bufB, sw2, out);
}

// round 16
// speedup vs baseline: 1.5870x; 1.1480x over previous
#include <cuda_runtime.h>
#include <cuda_fp16.h>
#include <math.h>
#include <stdint.h>

// Problem constants
#define T_TOK 49152          // B*S*N = 2*24*1024
#define HID   512
#define NEXP  8
#define MOEI  1024
#define SHI   2048
#define NSLOT (2 * T_TOK)    // top-2 -> exactly 2 slots per token

// ---------------------------------------------------------------------------
// Scratch (static __device__ arrays; no allocation anywhere)
// ---------------------------------------------------------------------------
__device__ __half g_bufA[100663296];            // h for MoE (2T x MOEI), fp16
__device__ __half g_bufB[100663296];            // h for shared (T x SHI), fp16
__device__ float  g_y [(size_t)NSLOT * HID];    // per-slot expert output (fp32)
__device__ int    g_topk_idx[NSLOT];
__device__ float  g_topk_w [NSLOT];
__device__ float  g_sig    [T_TOK];
__device__ int    g_counts [NEXP];
__device__ int    g_offsets[NEXP];
__device__ int    g_cursor [NEXP];
__device__ int    g_slot_token[NSLOT];          // slot -> token
__device__ int    g_slot_of   [NSLOT];          // (token,k) -> slot

// ---------------------------------------------------------------------------
// helpers
// ---------------------------------------------------------------------------
__device__ __forceinline__ uint32_t pack_h2(float lo, float hi) {
    __half2 h = __floats2half2_rn(lo, hi);
    return *(uint32_t*)&h;
}

__device__ __forceinline__ void mma_f16(float* c, const uint32_t* a,
                                        uint32_t b0, uint32_t b1) {
    asm volatile(
        "mma.sync.aligned.m16n8k16.row.col.f32.f16.f16.f32 "
        "{%0,%1,%2,%3},{%4,%5,%6,%7},{%8,%9},{%0,%1,%2,%3};"
        : "+f"(c[0]), "+f"(c[1]), "+f"(c[2]), "+f"(c[3])
        : "r"(a[0]), "r"(a[1]), "r"(a[2]), "r"(a[3]), "r"(b0), "r"(b1));
}

__device__ __forceinline__ float silu(float x) {
    return x * (1.f / (1.f + __expf(-x)));
}

// ---------------------------------------------------------------------------
// 0) zero counters
// ---------------------------------------------------------------------------
__global__ void init_kernel() {
    int i = threadIdx.x;
    if (i < NEXP) { g_counts[i] = 0; g_cursor[i] = 0; }
}

// ---------------------------------------------------------------------------
// 1) router (pure fp32 — expert selection bit-identical to reference path)
// ---------------------------------------------------------------------------
__global__ void __launch_bounds__(256) router_kernel(
    const float* __restrict__ x, const float* __restrict__ gw,
    const float* __restrict__ sg, float* __restrict__ logits_out)
{
    __shared__ float s_gw[HID * NEXP];
    __shared__ float s_sg[HID];
    for (int i = threadIdx.x; i < HID * NEXP; i += 256) s_gw[i] = gw[i];
    for (int i = threadIdx.x; i < HID; i += 256) s_sg[i] = sg[i];
    __syncthreads();

    int warp = threadIdx.x >> 5, lane = threadIdx.x & 31;
    int t = blockIdx.x * 8 + warp;
    const float* xr = x + (size_t)t * HID;

    float acc[NEXP];
#pragma unroll
    for (int e = 0; e < NEXP; e++) acc[e] = 0.f;
    float accs = 0.f;

#pragma unroll 4
    for (int i = 0; i < 16; i++) {
        int h = i * 32 + lane;
        float xv = xr[h];
#pragma unroll
        for (int e = 0; e < NEXP; e++) acc[e] += xv * s_gw[h * NEXP + e];
        accs += xv * s_sg[h];
    }
#pragma unroll
    for (int off = 16; off; off >>= 1) {
#pragma unroll
        for (int e = 0; e < NEXP; e++)
            acc[e] += __shfl_xor_sync(0xffffffff, acc[e], off);
        accs += __shfl_xor_sync(0xffffffff, accs, off);
    }

    if (lane == 0) {
        if (logits_out) {
#pragma unroll
            for (int e = 0; e < NEXP; e++) logits_out[(size_t)t * NEXP + e] = acc[e];
        }
        float m = acc[0];
#pragma unroll
        for (int e = 1; e < NEXP; e++) m = fmaxf(m, acc[e]);
        float p[NEXP], sum = 0.f;
#pragma unroll
        for (int e = 0; e < NEXP; e++) { p[e] = expf(acc[e] - m); sum += p[e]; }
        float inv = 1.f / sum;
#pragma unroll
        for (int e = 0; e < NEXP; e++) p[e] *= inv;

        int i1 = 0;
#pragma unroll
        for (int e = 1; e < NEXP; e++) if (p[e] > p[i1]) i1 = e;
        int i2 = (i1 == 0) ? 1 : 0;
#pragma unroll
        for (int e = 0; e < NEXP; e++) if (e != i1 && e != i2 && p[e] > p[i2]) i2 = e;

        g_topk_idx[2 * t]     = i1; g_topk_w[2 * t]     = p[i1];
        g_topk_idx[2 * t + 1] = i2; g_topk_w[2 * t + 1] = p[i2];
        atomicAdd(&g_counts[i1], 1);
        atomicAdd(&g_counts[i2], 1);
        g_sig[t] = 1.f / (1.f + expf(-accs));
    }
}

// ---------------------------------------------------------------------------
// 2) prefix, 3) scatter
// ---------------------------------------------------------------------------
__global__ void prefix_kernel() {
    if (threadIdx.x == 0) {
        int s = 0;
        for (int e = 0; e < NEXP; e++) { g_offsets[e] = s; g_cursor[e] = s; s += g_counts[e]; }
    }
}

__global__ void scatter_kernel() {
    int t = blockIdx.x * 256 + threadIdx.x;
    if (t >= T_TOK) return;
#pragma unroll
    for (int k = 0; k < 2; k++) {
        int e = g_topk_idx[2 * t + k];
        int pos = atomicAdd(&g_cursor[e], 1);
        g_slot_token[pos] = t;
        g_slot_of[2 * t + k] = pos;
    }
}

// ---------------------------------------------------------------------------
// 4a) dual fp16 GEMM + in-register SwiGLU, ping-pong smem.
//     C(half) = silu(A@B1) * (A@B3). Block 128x64, 8 warps 4(m)x2(n),
//     warp 32x32, mma.m16n8k16.f16 with fp32 accumulate. K-tile 32.
//     A smem: [128][40] halves (pitch 20 words, conflict-free frags).
//     B smem: k-paired half2 [16][72] per matrix (pitch%32==8 words).
//     z=0..7 MoE experts (gathered -> bufA), z=8..9 shared halves (-> bufB).
// ---------------------------------------------------------------------------
#define DUAL_AW   2560                      // A words per buffer (128*40/2)
#define DUAL_BW   1152                      // per-B-matrix words (16*72)
#define DUAL_BUFW (DUAL_AW + 2 * DUAL_BW)   // 4864 words
#define DUAL_SMEM (2 * DUAL_BUFW * 4)       // 38912 bytes

__global__ void __launch_bounds__(256, 2) dual_swiglu_kernel(
    const float* __restrict__ A,
    const float* __restrict__ W1m, const float* __restrict__ W3m, __half* __restrict__ Cm,
    const float* __restrict__ W1s, const float* __restrict__ W3s, __half* __restrict__ Cs)
{
    extern __shared__ uint32_t smu[];

    const int K = HID;
    int z = blockIdx.z;
    int M, base, N, col0, useGather;
    const float *B1p, *B3p;
    __half* C;
    if (z < NEXP) {
        M = g_counts[z]; base = g_offsets[z]; useGather = 1;
        N = MOEI; col0 = blockIdx.x * 64;
        B1p = W1m + (size_t)z * HID * MOEI;
        B3p = W3m + (size_t)z * HID * MOEI;
        C = Cm;
    } else {
        M = T_TOK; base = 0; useGather = 0;
        N = SHI; col0 = (blockIdx.x + (z - NEXP) * 16) * 64;
        B1p = W1s; B3p = W3s;
        C = Cs;
    }
    int row0 = blockIdx.y * 128;
    if (row0 >= M) return;

    int tid = threadIdx.x, lane = tid & 31, wid = tid >> 5;
    int wm = (wid >> 1) * 32, wn = (wid & 1) * 32;
    int g = lane >> 2, t = lane & 3;

    // A loader: 4 float4 units/thread: row = v>>3, kquad = v&7
    const float* aptr[4];
    int asto[4];
#pragma unroll
    for (int j = 0; j < 4; j++) {
        int v = tid + j * 256;
        int r = v >> 3, kq = v & 7;
        int gr = row0 + r; if (gr > M - 1) gr = M - 1;
        long arow = useGather ? (long)g_slot_token[base + gr] : (long)(base + gr);
        aptr[j] = A + (size_t)arow * K + kq * 4;
        asto[j] = r * 20 + kq * 2;
    }
    // B loader: 1 unit/thread/matrix: k-pair = tid>>4, n-quad = tid&15
    int bk2 = tid >> 4, bn4 = tid & 15;
    const float* b1p0 = B1p + (size_t)(2 * bk2) * N + col0 + bn4 * 4;
    const float* b3p0 = B3p + (size_t)(2 * bk2) * N + col0 + bn4 * 4;
    int bsto = bk2 * 72 + bn4 * 4;

    float accg[2][4][4], accu[2][4][4];
#pragma unroll
    for (int mi = 0; mi < 2; mi++)
#pragma unroll
        for (int ni = 0; ni < 4; ni++)
#pragma unroll
            for (int q = 0; q < 4; q++) { accg[mi][ni][q] = 0.f; accu[mi][ni][q] = 0.f; }

    const int nk = K >> 5;                  // 16

    float4 sa[4], s1a, s1b, s3a, s3b;
    auto fetch = [&]() {
#pragma unroll
        for (int j = 0; j < 4; j++) { sa[j] = *(const float4*)aptr[j]; aptr[j] += 32; }
        s1a = *(const float4*)b1p0; s1b = *(const float4*)(b1p0 + N); b1p0 += (size_t)32 * N;
        s3a = *(const float4*)b3p0; s3b = *(const float4*)(b3p0 + N); b3p0 += (size_t)32 * N;
    };
    auto stage = [&](uint32_t* buf) {
#pragma unroll
        for (int j = 0; j < 4; j++) {
            uint2 u;
            u.x = pack_h2(sa[j].x, sa[j].y);
            u.y = pack_h2(sa[j].z, sa[j].w);
            *(uint2*)&buf[asto[j]] = u;
        }
        uint32_t* b1 = buf + DUAL_AW;
        uint32_t* b3 = b1 + DUAL_BW;
        uint4 u1;
        u1.x = pack_h2(s1a.x, s1b.x); u1.y = pack_h2(s1a.y, s1b.y);
        u1.z = pack_h2(s1a.z, s1b.z); u1.w = pack_h2(s1a.w, s1b.w);
        *(uint4*)&b1[bsto] = u1;
        uint4 u3;
        u3.x = pack_h2(s3a.x, s3b.x); u3.y = pack_h2(s3a.y, s3b.y);
        u3.z = pack_h2(s3a.z, s3b.z); u3.w = pack_h2(s3a.w, s3b.w);
        *(uint4*)&b3[bsto] = u3;
    };

    fetch();
    stage(smu);
    __syncthreads();

    for (int kt = 0; kt < nk; kt++) {
        uint32_t* buf = smu + (kt & 1) * DUAL_BUFW;
        uint32_t* b1  = buf + DUAL_AW;
        uint32_t* b3  = b1 + DUAL_BW;

        if (kt + 1 < nk) fetch();

#pragma unroll
        for (int ks = 0; ks < 2; ks++) {
            uint32_t af[2][4];
#pragma unroll
            for (int mi = 0; mi < 2; mi++) {
                int r = wm + mi * 16 + g;
                int w0 = r * 20 + 8 * ks + t;
                int w1 = (r + 8) * 20 + 8 * ks + t;
                af[mi][0] = buf[w0];     af[mi][1] = buf[w1];
                af[mi][2] = buf[w0 + 4]; af[mi][3] = buf[w1 + 4];
            }
#pragma unroll
            for (int ni = 0; ni < 4; ni++) {
                int c = wn + ni * 8 + g;
                int wb0 = (8 * ks + t) * 72 + c;
                int wb1 = (8 * ks + t + 4) * 72 + c;
                uint32_t g0 = b1[wb0], g1 = b1[wb1];
                uint32_t u0 = b3[wb0], u1 = b3[wb1];
#pragma unroll
                for (int mi = 0; mi < 2; mi++) {
                    mma_f16(accg[mi][ni], af[mi], g0, g1);
                    mma_f16(accu[mi][ni], af[mi], u0, u1);
                }
            }
        }

        if (kt + 1 < nk) stage(smu + ((kt + 1) & 1) * DUAL_BUFW);
        __syncthreads();
    }

    // epilogue: h = silu(g) * u  (fp32 math, fp16 store)
#pragma unroll
    for (int mi = 0; mi < 2; mi++) {
        int r0 = row0 + wm + mi * 16 + g;
        int r1 = r0 + 8;
#pragma unroll
        for (int ni = 0; ni < 4; ni++) {
            int c = col0 + wn + ni * 8 + t * 2;
            if (r0 < M)
                *(uint32_t*)&C[(size_t)(base + r0) * N + c] =
                    pack_h2(silu(accg[mi][ni][0]) * accu[mi][ni][0],
                            silu(accg[mi][ni][1]) * accu[mi][ni][1]);
            if (r1 < M)
                *(uint32_t*)&C[(size_t)(base + r1) * N + c] =
                    pack_h2(silu(accg[mi][ni][2]) * accu[mi][ni][2],
                            silu(accg[mi][ni][3]) * accu[mi][ni][3]);
        }
    }
}

// ---------------------------------------------------------------------------
// 4b) fp16 down-projection GEMM, 128x128 tile, ping-pong smem.
//     A is fp16 (bufA/bufB). Templated K and FUSE.
//     FUSE=false: MoE y_slot -> g_y (fp32). FUSE=true: shared + combine -> out.
// ---------------------------------------------------------------------------
#define SG_AW   2560                        // A words per buffer (128*40/2)
#define SG_BW   2176                        // B words (16*136)
#define SG_BUFW (SG_AW + SG_BW)             // 4736 words
#define SG_SMEM (2 * SG_BUFW * 4)           // 37888 bytes

template<int KK, bool FUSE>
__global__ void __launch_bounds__(256, 2) sgemm_f16_kernel(
    const __half* __restrict__ A, const float* __restrict__ B, float* __restrict__ C)
{
    extern __shared__ uint32_t smu[];

    const int N = HID;
    int z = blockIdx.z;
    int M, base;
    const float* Bp;
    if (!FUSE) { M = g_counts[z]; base = g_offsets[z]; Bp = B + (size_t)z * KK * HID; }
    else       { M = T_TOK;       base = 0;            Bp = B; }
    int row0 = blockIdx.y * 128;
    if (row0 >= M) return;
    int col0 = blockIdx.x * 128;

    int tid = threadIdx.x, lane = tid & 31, wid = tid >> 5;
    int wm = (wid & 1) * 64, wn = (wid >> 1) * 32;
    int g = lane >> 2, t = lane & 3;

    // A loader (half source): 2 uint4 units/thread: row = v>>2, chunk = v&3
    const __half* aptr[2];
    int asto[2];
#pragma unroll
    for (int j = 0; j < 2; j++) {
        int v = tid + j * 256;
        int r = v >> 2, ch = v & 3;
        int gr = row0 + r; if (gr > M - 1) gr = M - 1;
        aptr[j] = A + (size_t)(base + gr) * KK + ch * 8;
        asto[j] = r * 20 + ch * 4;
    }
    // B loader (fp32 weights): 2 units/thread: k-pair = v>>5, n-quad = v&31
    const float* bptr[2];
    int bsto[2];
#pragma unroll
    for (int j = 0; j < 2; j++) {
        int v = tid + j * 256;
        bptr[j] = Bp + (size_t)(2 * (v >> 5)) * N + col0 + (v & 31) * 4;
        bsto[j] = (v >> 5) * 136 + (v & 31) * 4;
    }

    float acc[4][4][4];
#pragma unroll
    for (int mi = 0; mi < 4; mi++)
#pragma unroll
        for (int ni = 0; ni < 4; ni++)
#pragma unroll
            for (int q = 0; q < 4; q++) acc[mi][ni][q] = 0.f;

    const int nk = KK >> 5;

    uint4 sa[2];
    float4 sb0[2], sb1[2];
    auto fetch = [&]() {
#pragma unroll
        for (int j = 0; j < 2; j++) { sa[j] = *(const uint4*)aptr[j]; aptr[j] += 32; }
#pragma unroll
        for (int j = 0; j < 2; j++) {
            sb0[j] = *(const float4*)bptr[j];
            sb1[j] = *(const float4*)(bptr[j] + N);
            bptr[j] += (size_t)32 * N;
        }
    };
    auto stage = [&](uint32_t* buf) {
#pragma unroll
        for (int j = 0; j < 2; j++) *(uint4*)&buf[asto[j]] = sa[j];
        uint32_t* bb = buf + SG_AW;
#pragma unroll
        for (int j = 0; j < 2; j++) {
            uint4 u;
            u.x = pack_h2(sb0[j].x, sb1[j].x); u.y = pack_h2(sb0[j].y, sb1[j].y);
            u.z = pack_h2(sb0[j].z, sb1[j].z); u.w = pack_h2(sb0[j].w, sb1[j].w);
            *(uint4*)&bb[bsto[j]] = u;
        }
    };

    fetch();
    stage(smu);
    __syncthreads();

    for (int kt = 0; kt < nk; kt++) {
        uint32_t* buf = smu + (kt & 1) * SG_BUFW;
        uint32_t* bb  = buf + SG_AW;

        if (kt + 1 < nk) fetch();

#pragma unroll
        for (int ks = 0; ks < 2; ks++) {
            uint32_t af[4][4];
#pragma unroll
            for (int mi = 0; mi < 4; mi++) {
                int r = wm + mi * 16 + g;
                int w0 = r * 20 + 8 * ks + t;
                int w1 = (r + 8) * 20 + 8 * ks + t;
                af[mi][0] = buf[w0];     af[mi][1] = buf[w1];
                af[mi][2] = buf[w0 + 4]; af[mi][3] = buf[w1 + 4];
            }
#pragma unroll
            for (int ni = 0; ni < 4; ni++) {
                int c = wn + ni * 8 + g;
                uint32_t b0 = bb[(8 * ks + t) * 136 + c];
                uint32_t b1 = bb[(8 * ks + t + 4) * 136 + c];
#pragma unroll
                for (int mi = 0; mi < 4; mi++)
                    mma_f16(acc[mi][ni], af[mi], b0, b1);
            }
        }

        if (kt + 1 < nk) stage(smu + ((kt + 1) & 1) * SG_BUFW);
        __syncthreads();
    }

    // epilogue (fp32)
#pragma unroll
    for (int mi = 0; mi < 4; mi++) {
        int r0 = row0 + wm + mi * 16 + g;
        int r1 = r0 + 8;
#pragma unroll
        for (int ni = 0; ni < 4; ni++) {
            int c = col0 + wn + ni * 8 + t * 2;
            if (!FUSE) {
                if (r0 < M) {
                    float* p = C + (size_t)(base + r0) * N + c;
                    p[0] = acc[mi][ni][0]; p[1] = acc[mi][ni][1];
                }
                if (r1 < M) {
                    float* p = C + (size_t)(base + r1) * N + c;
                    p[0] = acc[mi][ni][2]; p[1] = acc[mi][ni][3];
                }
            } else {
                if (r0 < M) {
                    int tk = r0;
                    float w0 = g_topk_w[2 * tk], w1 = g_topk_w[2 * tk + 1];
                    int   s0 = g_slot_of[2 * tk], s1 = g_slot_of[2 * tk + 1];
                    float sg = g_sig[tk];
                    float2 y0 = *(const float2*)&g_y[(size_t)s0 * HID + c];
                    float2 y1 = *(const float2*)&g_y[(size_t)s1 * HID + c];
                    float* p = C + (size_t)tk * N + c;
                    p[0] = w0 * y0.x + w1 * y1.x + sg * acc[mi][ni][0];
                    p[1] = w0 * y0.y + w1 * y1.y + sg * acc[mi][ni][1];
                }
                if (r1 < M) {
                    int tk = r1;
                    float w0 = g_topk_w[2 * tk], w1 = g_topk_w[2 * tk + 1];
                    int   s0 = g_slot_of[2 * tk], s1 = g_slot_of[2 * tk + 1];
                    float sg = g_sig[tk];
                    float2 y0 = *(const float2*)&g_y[(size_t)s0 * HID + c];
                    float2 y1 = *(const float2*)&g_y[(size_t)s1 * HID + c];
                    float* p = C + (size_t)tk * N + c;
                    p[0] = w0 * y0.x + w1 * y1.x + sg * acc[mi][ni][2];
                    p[1] = w0 * y0.y + w1 * y1.y + sg * acc[mi][ni][3];
                }
            }
        }
    }
}

// ---------------------------------------------------------------------------
// launch
// ---------------------------------------------------------------------------
extern "C" void kernel_launch(void* const* d_in, const int* in_sizes, int n_in,
                              void* d_out, int out_size)
{
    const float* x     = (const float*)d_in[0];
    const float* gate  = (const float*)d_in[1];
    const float* w1    = (const float*)d_in[2];
    const float* w2    = (const float*)d_in[3];
    const float* w3    = (const float*)d_in[4];
    const float* sw1   = (const float*)d_in[5];
    const float* sw2   = (const float*)d_in[6];
    const float* sw3   = (const float*)d_in[7];
    const float* sgate = (const float*)d_in[8];
    float* out = (float*)d_out;

    float* logits = nullptr;
    if ((size_t)out_size >= (size_t)T_TOK * HID + (size_t)T_TOK * NEXP)
        logits = out + (size_t)T_TOK * HID;

    __half *bufA, *bufB;
    float* ybuf;
    cudaGetSymbolAddress((void**)&bufA, g_bufA);
    cudaGetSymbolAddress((void**)&bufB, g_bufB);
    cudaGetSymbolAddress((void**)&ybuf, g_y);

    init_kernel<<<1, 32>>>();
    router_kernel<<<T_TOK / 8, 256>>>(x, gate, sgate, logits);
    prefix_kernel<<<1, 32>>>();
    scatter_kernel<<<T_TOK / 256, 256>>>();

    // Stage A merged: z=0..7 MoE experts -> bufA (fp16), z=8..9 shared -> bufB
    dual_swiglu_kernel<<<dim3(16, T_TOK / 128, NEXP + 2), 256, DUAL_SMEM>>>(
        x, w1, w3, bufA, sw1, sw3, bufB);

    // Stage B launch 1: MoE down-proj -> g_y (fp32)
    sgemm_f16_kernel<MOEI, false><<<dim3(HID / 128, T_TOK / 128, NEXP), 256, SG_SMEM>>>(
        bufA, w2, ybuf);

    // Stage B launch 2: shared down-proj + fused final combine -> out
    sgemm_f16_kernel<SHI, true><<<dim3(HID / 128, T_TOK / 128, 1), 256, SG_SMEM>>>(
        bufB, sw2, out);
}

// round 17
// speedup vs baseline: 2.4142x; 1.5213x over previous
#include <cuda_runtime.h>
#include <cuda_fp16.h>
#include <math.h>
#include <stdint.h>

// Problem constants
#define T_TOK 49152          // B*S*N = 2*24*1024
#define HID   512
#define NEXP  8
#define MOEI  1024
#define SHI   2048
#define NSLOT (2 * T_TOK)    // top-2 -> exactly 2 slots per token

// ---------------------------------------------------------------------------
// Scratch (static __device__ arrays; no allocation anywhere)
// ---------------------------------------------------------------------------
__device__ __half g_bufA[100663296];            // h for MoE (2T x MOEI), fp16
__device__ __half g_bufB[100663296];            // h for shared (T x SHI), fp16
__device__ float  g_y [(size_t)NSLOT * HID];    // per-slot expert output (fp32)
__device__ int    g_topk_idx[NSLOT];
__device__ float  g_topk_w [NSLOT];
__device__ float  g_sig    [T_TOK];
__device__ int    g_counts [NEXP];
__device__ int    g_offsets[NEXP];
__device__ int    g_cursor [NEXP];
__device__ int    g_slot_token[NSLOT];          // slot -> token
__device__ int    g_slot_of   [NSLOT];          // (token,k) -> slot

// ---------------------------------------------------------------------------
// helpers
// ---------------------------------------------------------------------------
__device__ __forceinline__ uint32_t pack_h2(float lo, float hi) {
    __half2 h = __floats2half2_rn(lo, hi);
    return *(uint32_t*)&h;
}

__device__ __forceinline__ void mma_f16(float* c, const uint32_t* a,
                                        uint32_t b0, uint32_t b1) {
    asm volatile(
        "mma.sync.aligned.m16n8k16.row.col.f32.f16.f16.f32 "
        "{%0,%1,%2,%3},{%4,%5,%6,%7},{%8,%9},{%0,%1,%2,%3};"
        : "+f"(c[0]), "+f"(c[1]), "+f"(c[2]), "+f"(c[3])
        : "r"(a[0]), "r"(a[1]), "r"(a[2]), "r"(a[3]), "r"(b0), "r"(b1));
}

__device__ __forceinline__ float silu(float x) {
    return x * (1.f / (1.f + __expf(-x)));
}

// ---------------------------------------------------------------------------
// 0) zero counters
// ---------------------------------------------------------------------------
__global__ void init_kernel() {
    int i = threadIdx.x;
    if (i < NEXP) { g_counts[i] = 0; g_cursor[i] = 0; }
}

// ---------------------------------------------------------------------------
// 1) router (pure fp32 — expert selection bit-identical to reference path)
// ---------------------------------------------------------------------------
__global__ void __launch_bounds__(256) router_kernel(
    const float* __restrict__ x, const float* __restrict__ gw,
    const float* __restrict__ sg, float* __restrict__ logits_out)
{
    __shared__ float s_gw[HID * NEXP];
    __shared__ float s_sg[HID];
    for (int i = threadIdx.x; i < HID * NEXP; i += 256) s_gw[i] = gw[i];
    for (int i = threadIdx.x; i < HID; i += 256) s_sg[i] = sg[i];
    __syncthreads();

    int warp = threadIdx.x >> 5, lane = threadIdx.x & 31;
    int t = blockIdx.x * 8 + warp;
    const float* xr = x + (size_t)t * HID;

    float acc[NEXP];
#pragma unroll
    for (int e = 0; e < NEXP; e++) acc[e] = 0.f;
    float accs = 0.f;

#pragma unroll 4
    for (int i = 0; i < 16; i++) {
        int h = i * 32 + lane;
        float xv = xr[h];
#pragma unroll
        for (int e = 0; e < NEXP; e++) acc[e] += xv * s_gw[h * NEXP + e];
        accs += xv * s_sg[h];
    }
#pragma unroll
    for (int off = 16; off; off >>= 1) {
#pragma unroll
        for (int e = 0; e < NEXP; e++)
            acc[e] += __shfl_xor_sync(0xffffffff, acc[e], off);
        accs += __shfl_xor_sync(0xffffffff, accs, off);
    }

    if (lane == 0) {
        if (logits_out) {
#pragma unroll
            for (int e = 0; e < NEXP; e++) logits_out[(size_t)t * NEXP + e] = acc[e];
        }
        float m = acc[0];
#pragma unroll
        for (int e = 1; e < NEXP; e++) m = fmaxf(m, acc[e]);
        float p[NEXP], sum = 0.f;
#pragma unroll
        for (int e = 0; e < NEXP; e++) { p[e] = expf(acc[e] - m); sum += p[e]; }
        float inv = 1.f / sum;
#pragma unroll
        for (int e = 0; e < NEXP; e++) p[e] *= inv;

        int i1 = 0;
#pragma unroll
        for (int e = 1; e < NEXP; e++) if (p[e] > p[i1]) i1 = e;
        int i2 = (i1 == 0) ? 1 : 0;
#pragma unroll
        for (int e = 0; e < NEXP; e++) if (e != i1 && e != i2 && p[e] > p[i2]) i2 = e;

        g_topk_idx[2 * t]     = i1; g_topk_w[2 * t]     = p[i1];
        g_topk_idx[2 * t + 1] = i2; g_topk_w[2 * t + 1] = p[i2];
        atomicAdd(&g_counts[i1], 1);
        atomicAdd(&g_counts[i2], 1);
        g_sig[t] = 1.f / (1.f + expf(-accs));
    }
}

// ---------------------------------------------------------------------------
// 2) prefix, 3) scatter
// ---------------------------------------------------------------------------
__global__ void prefix_kernel() {
    if (threadIdx.x == 0) {
        int s = 0;
        for (int e = 0; e < NEXP; e++) { g_offsets[e] = s; g_cursor[e] = s; s += g_counts[e]; }
    }
}

__global__ void scatter_kernel() {
    int t = blockIdx.x * 256 + threadIdx.x;
    if (t >= T_TOK) return;
#pragma unroll
    for (int k = 0; k < 2; k++) {
        int e = g_topk_idx[2 * t + k];
        int pos = atomicAdd(&g_cursor[e], 1);
        g_slot_token[pos] = t;
        g_slot_of[2 * t + k] = pos;
    }
}

// ---------------------------------------------------------------------------
// 4a) dual fp16 GEMM + in-register SwiGLU, ping-pong smem, 512 threads.
//     Tile 128(M) x 128(N per matrix), 16 warps 4m x 4n, warp 32x32 dual.
//     A smem: [128][40] halves (pitch 20 words). B: k-paired half2,
//     [16][136] words per matrix. K-tile 32.
//     z=0..7 MoE experts (gathered -> bufA), z=8..9 shared halves (-> bufB).
// ---------------------------------------------------------------------------
#define DUAL_AW   2560                      // A words per buffer (128*20)
#define DUAL_BW   2176                      // per-B-matrix words (16*136)
#define DUAL_BUFW (DUAL_AW + 2 * DUAL_BW)   // 6912 words
#define DUAL_SMEM (2 * DUAL_BUFW * 4)       // 55296 bytes

__global__ void __launch_bounds__(512, 1) dual_swiglu_kernel(
    const float* __restrict__ A,
    const float* __restrict__ W1m, const float* __restrict__ W3m, __half* __restrict__ Cm,
    const float* __restrict__ W1s, const float* __restrict__ W3s, __half* __restrict__ Cs)
{
    extern __shared__ uint32_t smu[];

    const int K = HID;
    int z = blockIdx.z;
    int M, base, N, col0, useGather;
    const float *B1p, *B3p;
    __half* C;
    if (z < NEXP) {
        M = g_counts[z]; base = g_offsets[z]; useGather = 1;
        N = MOEI; col0 = blockIdx.x * 128;
        B1p = W1m + (size_t)z * HID * MOEI;
        B3p = W3m + (size_t)z * HID * MOEI;
        C = Cm;
    } else {
        M = T_TOK; base = 0; useGather = 0;
        N = SHI; col0 = (blockIdx.x + (z - NEXP) * 8) * 128;
        B1p = W1s; B3p = W3s;
        C = Cs;
    }
    int row0 = blockIdx.y * 128;
    if (row0 >= M) return;

    int tid = threadIdx.x, lane = tid & 31, wid = tid >> 5;
    int wm = (wid >> 2) * 32, wn = (wid & 3) * 32;
    int g = lane >> 2, t = lane & 3;

    // A loader: 2 float4 units/thread: v -> row = v>>3, kquad = v&7
    const float* aptr[2];
    int asto[2];
#pragma unroll
    for (int j = 0; j < 2; j++) {
        int v = tid + j * 512;
        int r = v >> 3, kq = v & 7;
        int gr = row0 + r; if (gr > M - 1) gr = M - 1;
        long arow = useGather ? (long)g_slot_token[base + gr] : (long)(base + gr);
        aptr[j] = A + (size_t)arow * K + kq * 4;
        asto[j] = r * 20 + kq * 2;
    }
    // B loader: 1 unit/thread/matrix: k-pair = tid>>5, n-quad = tid&31
    int bk2 = tid >> 5, bn4 = tid & 31;
    const float* b1p0 = B1p + (size_t)(2 * bk2) * N + col0 + bn4 * 4;
    const float* b3p0 = B3p + (size_t)(2 * bk2) * N + col0 + bn4 * 4;
    int bsto = bk2 * 136 + bn4 * 4;

    float accg[2][4][4], accu[2][4][4];
#pragma unroll
    for (int mi = 0; mi < 2; mi++)
#pragma unroll
        for (int ni = 0; ni < 4; ni++)
#pragma unroll
            for (int q = 0; q < 4; q++) { accg[mi][ni][q] = 0.f; accu[mi][ni][q] = 0.f; }

    const int nk = K >> 5;                  // 16

    float4 sa[2], s1a, s1b, s3a, s3b;
    auto fetch = [&]() {
#pragma unroll
        for (int j = 0; j < 2; j++) { sa[j] = *(const float4*)aptr[j]; aptr[j] += 32; }
        s1a = *(const float4*)b1p0; s1b = *(const float4*)(b1p0 + N); b1p0 += (size_t)32 * N;
        s3a = *(const float4*)b3p0; s3b = *(const float4*)(b3p0 + N); b3p0 += (size_t)32 * N;
    };
    auto stage = [&](uint32_t* buf) {
#pragma unroll
        for (int j = 0; j < 2; j++) {
            uint2 u;
            u.x = pack_h2(sa[j].x, sa[j].y);
            u.y = pack_h2(sa[j].z, sa[j].w);
            *(uint2*)&buf[asto[j]] = u;
        }
        uint32_t* b1 = buf + DUAL_AW;
        uint32_t* b3 = b1 + DUAL_BW;
        uint4 u1;
        u1.x = pack_h2(s1a.x, s1b.x); u1.y = pack_h2(s1a.y, s1b.y);
        u1.z = pack_h2(s1a.z, s1b.z); u1.w = pack_h2(s1a.w, s1b.w);
        *(uint4*)&b1[bsto] = u1;
        uint4 u3;
        u3.x = pack_h2(s3a.x, s3b.x); u3.y = pack_h2(s3a.y, s3b.y);
        u3.z = pack_h2(s3a.z, s3b.z); u3.w = pack_h2(s3a.w, s3b.w);
        *(uint4*)&b3[bsto] = u3;
    };

    fetch();
    stage(smu);
    __syncthreads();

    for (int kt = 0; kt < nk; kt++) {
        uint32_t* buf = smu + (kt & 1) * DUAL_BUFW;
        uint32_t* b1  = buf + DUAL_AW;
        uint32_t* b3  = b1 + DUAL_BW;

        if (kt + 1 < nk) fetch();

#pragma unroll
        for (int ks = 0; ks < 2; ks++) {
            uint32_t af[2][4];
#pragma unroll
            for (int mi = 0; mi < 2; mi++) {
                int r = wm + mi * 16 + g;
                int w0 = r * 20 + 8 * ks + t;
                int w1 = (r + 8) * 20 + 8 * ks + t;
                af[mi][0] = buf[w0];     af[mi][1] = buf[w1];
                af[mi][2] = buf[w0 + 4]; af[mi][3] = buf[w1 + 4];
            }
#pragma unroll
            for (int ni = 0; ni < 4; ni++) {
                int c = wn + ni * 8 + g;
                int wb0 = (8 * ks + t) * 136 + c;
                int wb1 = (8 * ks + t + 4) * 136 + c;
                uint32_t g0 = b1[wb0], g1 = b1[wb1];
                uint32_t u0 = b3[wb0], u1 = b3[wb1];
#pragma unroll
                for (int mi = 0; mi < 2; mi++) {
                    mma_f16(accg[mi][ni], af[mi], g0, g1);
                    mma_f16(accu[mi][ni], af[mi], u0, u1);
                }
            }
        }

        if (kt + 1 < nk) stage(smu + ((kt + 1) & 1) * DUAL_BUFW);
        __syncthreads();
    }

    // epilogue: h = silu(g) * u  (fp32 math, fp16 store)
#pragma unroll
    for (int mi = 0; mi < 2; mi++) {
        int r0 = row0 + wm + mi * 16 + g;
        int r1 = r0 + 8;
#pragma unroll
        for (int ni = 0; ni < 4; ni++) {
            int c = col0 + wn + ni * 8 + t * 2;
            if (r0 < M)
                *(uint32_t*)&C[(size_t)(base + r0) * N + c] =
                    pack_h2(silu(accg[mi][ni][0]) * accu[mi][ni][0],
                            silu(accg[mi][ni][1]) * accu[mi][ni][1]);
            if (r1 < M)
                *(uint32_t*)&C[(size_t)(base + r1) * N + c] =
                    pack_h2(silu(accg[mi][ni][2]) * accu[mi][ni][2],
                            silu(accg[mi][ni][3]) * accu[mi][ni][3]);
        }
    }
}

// ---------------------------------------------------------------------------
// 4b) fp16 down-projection GEMM, 256x128 tile, 512 threads, ping-pong smem.
//     16 warps 8m x 2n, warp 32x64. A is fp16. Templated K and FUSE.
//     FUSE=false: MoE y_slot -> g_y (fp32). FUSE=true: shared + combine -> out.
// ---------------------------------------------------------------------------
#define SG_AW   5120                        // A words per buffer (256*20)
#define SG_BW   2176                        // B words (16*136)
#define SG_BUFW (SG_AW + SG_BW)             // 7296 words
#define SG_SMEM (2 * SG_BUFW * 4)           // 58368 bytes

template<int KK, bool FUSE>
__global__ void __launch_bounds__(512, 1) sgemm_f16_kernel(
    const __half* __restrict__ A, const float* __restrict__ B, float* __restrict__ C)
{
    extern __shared__ uint32_t smu[];

    const int N = HID;
    int z = blockIdx.z;
    int M, base;
    const float* Bp;
    if (!FUSE) { M = g_counts[z]; base = g_offsets[z]; Bp = B + (size_t)z * KK * HID; }
    else       { M = T_TOK;       base = 0;            Bp = B; }
    int row0 = blockIdx.y * 256;
    if (row0 >= M) return;
    int col0 = blockIdx.x * 128;

    int tid = threadIdx.x, lane = tid & 31, wid = tid >> 5;
    int wm = (wid >> 1) * 32, wn = (wid & 1) * 64;
    int g = lane >> 2, t = lane & 3;

    // A loader (half source): 2 uint4 units/thread: row = v>>2, chunk = v&3
    const __half* aptr[2];
    int asto[2];
#pragma unroll
    for (int j = 0; j < 2; j++) {
        int v = tid + j * 512;
        int r = v >> 2, ch = v & 3;
        int gr = row0 + r; if (gr > M - 1) gr = M - 1;
        aptr[j] = A + (size_t)(base + gr) * KK + ch * 8;
        asto[j] = r * 20 + ch * 4;
    }
    // B loader (fp32 weights): 1 unit/thread: k-pair = tid>>5, n-quad = tid&31
    int bk2 = tid >> 5, bn4 = tid & 31;
    const float* bp0 = Bp + (size_t)(2 * bk2) * N + col0 + bn4 * 4;
    int bsto = bk2 * 136 + bn4 * 4;

    float acc[2][8][4];
#pragma unroll
    for (int mi = 0; mi < 2; mi++)
#pragma unroll
        for (int ni = 0; ni < 8; ni++)
#pragma unroll
            for (int q = 0; q < 4; q++) acc[mi][ni][q] = 0.f;

    const int nk = KK >> 5;

    uint4 sa[2];
    float4 sb0, sb1;
    auto fetch = [&]() {
#pragma unroll
        for (int j = 0; j < 2; j++) { sa[j] = *(const uint4*)aptr[j]; aptr[j] += 32; }
        sb0 = *(const float4*)bp0;
        sb1 = *(const float4*)(bp0 + N);
        bp0 += (size_t)32 * N;
    };
    auto stage = [&](uint32_t* buf) {
#pragma unroll
        for (int j = 0; j < 2; j++) *(uint4*)&buf[asto[j]] = sa[j];
        uint32_t* bb = buf + SG_AW;
        uint4 u;
        u.x = pack_h2(sb0.x, sb1.x); u.y = pack_h2(sb0.y, sb1.y);
        u.z = pack_h2(sb0.z, sb1.z); u.w = pack_h2(sb0.w, sb1.w);
        *(uint4*)&bb[bsto] = u;
    };

    fetch();
    stage(smu);
    __syncthreads();

    for (int kt = 0; kt < nk; kt++) {
        uint32_t* buf = smu + (kt & 1) * SG_BUFW;
        uint32_t* bb  = buf + SG_AW;

        if (kt + 1 < nk) fetch();

#pragma unroll
        for (int ks = 0; ks < 2; ks++) {
            uint32_t af[2][4];
#pragma unroll
            for (int mi = 0; mi < 2; mi++) {
                int r = wm + mi * 16 + g;
                int w0 = r * 20 + 8 * ks + t;
                int w1 = (r + 8) * 20 + 8 * ks + t;
                af[mi][0] = buf[w0];     af[mi][1] = buf[w1];
                af[mi][2] = buf[w0 + 4]; af[mi][3] = buf[w1 + 4];
            }
#pragma unroll
            for (int ni = 0; ni < 8; ni++) {
                int c = wn + ni * 8 + g;
                uint32_t b0 = bb[(8 * ks + t) * 136 + c];
                uint32_t b1 = bb[(8 * ks + t + 4) * 136 + c];
#pragma unroll
                for (int mi = 0; mi < 2; mi++)
                    mma_f16(acc[mi][ni], af[mi], b0, b1);
            }
        }

        if (kt + 1 < nk) stage(smu + ((kt + 1) & 1) * SG_BUFW);
        __syncthreads();
    }

    // epilogue (fp32)
#pragma unroll
    for (int mi = 0; mi < 2; mi++) {
        int r0 = row0 + wm + mi * 16 + g;
        int r1 = r0 + 8;
#pragma unroll
        for (int ni = 0; ni < 8; ni++) {
            int c = col0 + wn + ni * 8 + t * 2;
            if (!FUSE) {
                if (r0 < M) {
                    float* p = C + (size_t)(base + r0) * N + c;
                    p[0] = acc[mi][ni][0]; p[1] = acc[mi][ni][1];
                }
                if (r1 < M) {
                    float* p = C + (size_t)(base + r1) * N + c;
                    p[0] = acc[mi][ni][2]; p[1] = acc[mi][ni][3];
                }
            } else {
                if (r0 < M) {
                    int tk = r0;
                    float w0 = g_topk_w[2 * tk], w1 = g_topk_w[2 * tk + 1];
                    int   s0 = g_slot_of[2 * tk], s1 = g_slot_of[2 * tk + 1];
                    float sg = g_sig[tk];
                    float2 y0 = *(const float2*)&g_y[(size_t)s0 * HID + c];
                    float2 y1 = *(const float2*)&g_y[(size_t)s1 * HID + c];
                    float* p = C + (size_t)tk * N + c;
                    p[0] = w0 * y0.x + w1 * y1.x + sg * acc[mi][ni][0];
                    p[1] = w0 * y0.y + w1 * y1.y + sg * acc[mi][ni][1];
                }
                if (r1 < M) {
                    int tk = r1;
                    float w0 = g_topk_w[2 * tk], w1 = g_topk_w[2 * tk + 1];
                    int   s0 = g_slot_of[2 * tk], s1 = g_slot_of[2 * tk + 1];
                    float sg = g_sig[tk];
                    float2 y0 = *(const float2*)&g_y[(size_t)s0 * HID + c];
                    float2 y1 = *(const float2*)&g_y[(size_t)s1 * HID + c];
                    float* p = C + (size_t)tk * N + c;
                    p[0] = w0 * y0.x + w1 * y1.x + sg * acc[mi][ni][2];
                    p[1] = w0 * y0.y + w1 * y1.y + sg * acc[mi][ni][3];
                }
            }
        }
    }
}

// ---------------------------------------------------------------------------
// launch
// ---------------------------------------------------------------------------
extern "C" void kernel_launch(void* const* d_in, const int* in_sizes, int n_in,
                              void* d_out, int out_size)
{
    const float* x     = (const float*)d_in[0];
    const float* gate  = (const float*)d_in[1];
    const float* w1    = (const float*)d_in[2];
    const float* w2    = (const float*)d_in[3];
    const float* w3    = (const float*)d_in[4];
    const float* sw1   = (const float*)d_in[5];
    const float* sw2   = (const float*)d_in[6];
    const float* sw3   = (const float*)d_in[7];
    const float* sgate = (const float*)d_in[8];
    float* out = (float*)d_out;

    float* logits = nullptr;
    if ((size_t)out_size >= (size_t)T_TOK * HID + (size_t)T_TOK * NEXP)
        logits = out + (size_t)T_TOK * HID;

    __half *bufA, *bufB;
    float* ybuf;
    cudaGetSymbolAddress((void**)&bufA, g_bufA);
    cudaGetSymbolAddress((void**)&bufB, g_bufB);
    cudaGetSymbolAddress((void**)&ybuf, g_y);

    static int smem_set = 0;
    if (!smem_set) {
        cudaFuncSetAttribute(dual_swiglu_kernel,
                             cudaFuncAttributeMaxDynamicSharedMemorySize, DUAL_SMEM);
        cudaFuncSetAttribute(sgemm_f16_kernel<MOEI, false>,
                             cudaFuncAttributeMaxDynamicSharedMemorySize, SG_SMEM);
        cudaFuncSetAttribute(sgemm_f16_kernel<SHI, true>,
                             cudaFuncAttributeMaxDynamicSharedMemorySize, SG_SMEM);
        smem_set = 1;
    }

    init_kernel<<<1, 32>>>();
    router_kernel<<<T_TOK / 8, 256>>>(x, gate, sgate, logits);
    prefix_kernel<<<1, 32>>>();
    scatter_kernel<<<T_TOK / 256, 256>>>();

    // Stage A merged: z=0..7 MoE experts -> bufA (fp16), z=8..9 shared -> bufB
    dual_swiglu_kernel<<<dim3(8, T_TOK / 128, NEXP + 2), 512, DUAL_SMEM>>>(
        x, w1, w3, bufA, sw1, sw3, bufB);

    // Stage B launch 1: MoE down-proj -> g_y (fp32)
    sgemm_f16_kernel<MOEI, false><<<dim3(HID / 128, T_TOK / 256, NEXP), 512, SG_SMEM>>>(
        bufA, w2, ybuf);

    // Stage B launch 2: shared down-proj + fused final combine -> out
    sgemm_f16_kernel<SHI, true><<<dim3(HID / 128, T_TOK / 256, 1), 512, SG_SMEM>>>(
        bufB, sw2, out);
}